// round 8
// baseline (speedup 1.0000x reference)
#include <cuda_runtime.h>
#include <cuda_bf16.h>

#define BB    128
#define TT    512
#define FEAT  96
#define GATES 768
#define HID   192
#define NCLS  250

// scratch (device globals; allocations are forbidden)
__device__ __align__(16) float g_feat[BB * TT * FEAT];     // 25 MB
__device__ __align__(16) float g_pre [BB * TT * GATES];    // 201 MB (streamed, evict-first)
__device__ __align__(16) float g_hs  [BB * TT * HID];      // 50 MB  (kept L2-resident)

// ---------------- packed f32x2 helpers ----------------
__device__ __forceinline__ unsigned long long pack2(float x, float y) {
    unsigned long long u;
    asm("mov.b64 %0, {%1, %2};" : "=l"(u) : "f"(x), "f"(y));
    return u;
}
__device__ __forceinline__ unsigned long long ffma2(unsigned long long a,
                                                    unsigned long long b,
                                                    unsigned long long c) {
    unsigned long long d;
    asm("fma.rn.f32x2 %0, %1, %2, %3;" : "=l"(d) : "l"(a), "l"(b), "l"(c));
    return d;
}
__device__ __forceinline__ float pairsum(unsigned long long a) {
    float x, y;
    asm("mov.b64 {%0, %1}, %2;" : "=f"(x), "=f"(y) : "l"(a));
    return x + y;
}
__device__ __forceinline__ float tanh_apx(float x) {
    float y;
    asm("tanh.approx.f32 %0, %1;" : "=f"(y) : "f"(x));
    return y;
}
__device__ __forceinline__ float sig_apx(float x) {
    return fmaf(tanh_apx(0.5f * x), 0.5f, 0.5f);
}

// ---------------------------------------------------------------------------
// K1: feature prep. One thread per (b,t).
// layout per (b,t): [0:42] right hand, [42:48] right arm, [48:90] left hand,
//                   [90:96] left arm   (matches LSTM order rh,ra,lh,la)
// ---------------------------------------------------------------------------
__global__ void __launch_bounds__(256) k_feat(const float* __restrict__ x) {
    int idx = blockIdx.x * 256 + threadIdx.x;
    if (idx >= BB * TT) return;
    const float* row = x + (size_t)idx * 266;
    float* out = g_feat + (size_t)idx * FEAT;

    // right hand: points 112..132 (floats 224..265), ref point 10 (floats 20,21)
    {
        float rx = row[20], ry = row[21];
        float mnx = 1e30f, mxx = -1e30f, mny = 1e30f, mxy = -1e30f;
        #pragma unroll
        for (int p = 0; p < 21; p++) {
            float px = row[224 + 2 * p], py = row[225 + 2 * p];
            mnx = fminf(mnx, px); mxx = fmaxf(mxx, px);
            mny = fminf(mny, py); mxy = fmaxf(mxy, py);
        }
        float s = fmaxf(mxx - mnx, mxy - mny);
        s = (s == 0.f) ? 1.f : s;
        float inv = 1.f / s;
        #pragma unroll
        for (int p = 0; p < 21; p++) {
            out[2 * p]     = (row[224 + 2 * p] - rx) * inv;
            out[2 * p + 1] = (row[225 + 2 * p] - ry) * inv;
        }
    }
    // right arm: points 6,8,10 (floats 12,16,20), ref point 0
    {
        float cx = row[0], cy = row[1];
        float x0 = row[12], y0 = row[13];
        float x1 = row[16], y1 = row[17];
        float x2 = row[20], y2 = row[21];
        float w = fmaxf(fmaxf(x0, x1), x2) - fminf(fminf(x0, x1), x2);
        float h = fmaxf(fmaxf(y0, y1), y2) - fminf(fminf(y0, y1), y2);
        float s = fmaxf(w, h); s = (s == 0.f) ? 1.f : s;
        float inv = 1.f / s;
        out[42] = (x0 - cx) * inv; out[43] = (y0 - cy) * inv;
        out[44] = (x1 - cx) * inv; out[45] = (y1 - cy) * inv;
        out[46] = (x2 - cx) * inv; out[47] = (y2 - cy) * inv;
    }
    // left hand: points 91..111 (floats 182..223), ref point 9 (floats 18,19)
    {
        float rx = row[18], ry = row[19];
        float mnx = 1e30f, mxx = -1e30f, mny = 1e30f, mxy = -1e30f;
        #pragma unroll
        for (int p = 0; p < 21; p++) {
            float px = row[182 + 2 * p], py = row[183 + 2 * p];
            mnx = fminf(mnx, px); mxx = fmaxf(mxx, px);
            mny = fminf(mny, py); mxy = fmaxf(mxy, py);
        }
        float s = fmaxf(mxx - mnx, mxy - mny);
        s = (s == 0.f) ? 1.f : s;
        float inv = 1.f / s;
        #pragma unroll
        for (int p = 0; p < 21; p++) {
            out[48 + 2 * p] = (row[182 + 2 * p] - rx) * inv;
            out[49 + 2 * p] = (row[183 + 2 * p] - ry) * inv;
        }
    }
    // left arm: points 5,7,9 (floats 10,14,18), ref point 0
    {
        float cx = row[0], cy = row[1];
        float x0 = row[10], y0 = row[11];
        float x1 = row[14], y1 = row[15];
        float x2 = row[18], y2 = row[19];
        float w = fmaxf(fmaxf(x0, x1), x2) - fminf(fminf(x0, x1), x2);
        float h = fmaxf(fmaxf(y0, y1), y2) - fminf(fminf(y0, y1), y2);
        float s = fmaxf(w, h); s = (s == 0.f) ? 1.f : s;
        float inv = 1.f / s;
        out[90] = (x0 - cx) * inv; out[91] = (y0 - cy) * inv;
        out[92] = (x1 - cx) * inv; out[93] = (y1 - cy) * inv;
        out[94] = (x2 - cx) * inv; out[95] = (y2 - cy) * inv;
    }
}

// ---------------------------------------------------------------------------
// K2: input GEMM.  pre[b][t][g] = (bih+bhh) + wih_row . feat
// 768 threads = one output column each (warp stores 128B coalesced).
// pre stored with .cs so the 201MB stream doesn't evict g_hs from L2.
// ---------------------------------------------------------------------------
__global__ void __launch_bounds__(768)
k_ingemm(const float* __restrict__ wih_rh, const float* __restrict__ bih_rh, const float* __restrict__ bhh_rh,
         const float* __restrict__ wih_ra, const float* __restrict__ bih_ra, const float* __restrict__ bhh_ra,
         const float* __restrict__ wih_lh, const float* __restrict__ bih_lh, const float* __restrict__ bhh_lh,
         const float* __restrict__ wih_la, const float* __restrict__ bih_la, const float* __restrict__ bhh_la) {
    __shared__ __align__(16) float fs[128 * FEAT];   // 48 KB
    int b  = blockIdx.x >> 2;
    int t0 = (blockIdx.x & 3) << 7;
    int g  = threadIdx.x;

    const float4* src4 = (const float4*)(g_feat + ((size_t)b * TT + t0) * FEAT);
    float4* dst4 = (float4*)fs;
    for (int i = g; i < 128 * FEAT / 4; i += 768) dst4[i] = src4[i];

    int r, F, k0, H;
    const float *wih, *bih, *bhh;
    if (g < 256)      { r = g;       F = 42; k0 = 0;  H = 64; wih = wih_rh; bih = bih_rh; bhh = bhh_rh; }
    else if (g < 384) { r = g - 256; F = 6;  k0 = 42; H = 32; wih = wih_ra; bih = bih_ra; bhh = bhh_ra; }
    else if (g < 640) { r = g - 384; F = 42; k0 = 48; H = 64; wih = wih_lh; bih = bih_lh; bhh = bhh_lh; }
    else              { r = g - 640; F = 6;  k0 = 90; H = 32; wih = wih_la; bih = bih_la; bhh = bhh_la; }
    int ul = r >> 2, gate = r & 3;
    int row = gate * H + ul;
    float bias = bih[row] + bhh[row];
    float* po = g_pre + ((size_t)b * TT + t0) * GATES + g;
    __syncthreads();

    if (F == 42) {
        unsigned long long w[21];
        const float* wr = wih + row * 42;
        #pragma unroll
        for (int i = 0; i < 21; i++) {
            float2 v = *(const float2*)(wr + 2 * i);
            w[i] = pack2(v.x, v.y);
        }
        #pragma unroll 2
        for (int t = 0; t < 128; t++) {
            const float* fp = fs + t * FEAT + k0;   // 16B aligned (k0 = 0 or 48)
            unsigned long long aA = 0ull, aB = 0ull;
            #pragma unroll
            for (int i = 0; i < 10; i++) {
                ulonglong2 q = *(const ulonglong2*)(fp + 4 * i);
                aA = ffma2(w[2 * i],     q.x, aA);
                aB = ffma2(w[2 * i + 1], q.y, aB);
            }
            unsigned long long tail = *(const unsigned long long*)(fp + 40);
            aA = ffma2(w[20], tail, aA);
            __stcs(po + (size_t)t * GATES, bias + pairsum(aA) + pairsum(aB));
        }
    } else {
        unsigned long long w[3];
        const float* wr = wih + row * 6;
        #pragma unroll
        for (int i = 0; i < 3; i++) {
            float2 v = *(const float2*)(wr + 2 * i);
            w[i] = pack2(v.x, v.y);
        }
        #pragma unroll 2
        for (int t = 0; t < 128; t++) {
            const unsigned long long* f2 = (const unsigned long long*)(fs + t * FEAT + k0);
            unsigned long long a = 0ull;
            #pragma unroll
            for (int i = 0; i < 3; i++) a = ffma2(w[i], f2[i], a);
            __stcs(po + (size_t)t * GATES, bias + pairsum(a));
        }
    }
}

// ---------------------------------------------------------------------------
// K3: recurrent scan.  512 CTAs = one per (sample, segment) -- the four LSTMs
// are independent, so each gets its own CTA.  128 threads/CTA:
//   hands (H=64): 2 threads/unit, arms (H=32): 4 threads/unit.
// Recurrent weights in registers; h double-buffered in smem; q==0 lane holds
// cell state, reads pre as float4 via a depth-4 register prefetch ring (.cs).
// ---------------------------------------------------------------------------
template<int H, int Q, int PB, int HB>
__device__ __forceinline__ void scan_cta(const float* __restrict__ whh, int b,
                                         float (*hsm)[64]) {
    constexpr int SL = H / Q;    // floats per slice
    constexpr int NH = SL / 2;   // u64 per gate
    constexpr int NV = NH / 2;   // ulonglong2 per gate
    int tid = threadIdx.x;
    int ul = tid / Q, q = tid % Q;

    unsigned long long w[4 * NH];
    #pragma unroll
    for (int gI = 0; gI < 4; gI++) {
        const float* rw = whh + (gI * H + ul) * H + q * SL;
        #pragma unroll
        for (int i = 0; i < NH; i++) {
            float2 v = *(const float2*)(rw + 2 * i);
            w[gI * NH + i] = pack2(v.x, v.y);
        }
    }
    const float4* pp = (const float4*)(g_pre + (size_t)b * TT * GATES + PB + ul * 4);
    float* hout = g_hs + (size_t)b * TT * HID + HB + ul;
    float c = 0.f;

    if (tid < H) hsm[0][tid] = 0.f;
    __syncthreads();

    auto step = [&](int t, float4 cur) {
        const ulonglong2* hv = (const ulonglong2*)&hsm[t & 1][q * SL];
        unsigned long long a0 = 0ull, a1 = 0ull, a2 = 0ull, a3 = 0ull;
        #pragma unroll
        for (int i = 0; i < NV; i++) {
            ulonglong2 hq = hv[i];
            a0 = ffma2(w[0 * NH + 2 * i],     hq.x, a0);
            a0 = ffma2(w[0 * NH + 2 * i + 1], hq.y, a0);
            a1 = ffma2(w[1 * NH + 2 * i],     hq.x, a1);
            a1 = ffma2(w[1 * NH + 2 * i + 1], hq.y, a1);
            a2 = ffma2(w[2 * NH + 2 * i],     hq.x, a2);
            a2 = ffma2(w[2 * NH + 2 * i + 1], hq.y, a2);
            a3 = ffma2(w[3 * NH + 2 * i],     hq.x, a3);
            a3 = ffma2(w[3 * NH + 2 * i + 1], hq.y, a3);
        }
        float p0 = pairsum(a0), p1 = pairsum(a1), p2 = pairsum(a2), p3 = pairsum(a3);
        #pragma unroll
        for (int o = 1; o < Q; o <<= 1) {
            p0 += __shfl_xor_sync(0xffffffffu, p0, o);
            p1 += __shfl_xor_sync(0xffffffffu, p1, o);
            p2 += __shfl_xor_sync(0xffffffffu, p2, o);
            p3 += __shfl_xor_sync(0xffffffffu, p3, o);
        }
        if (q == 0) {
            p0 += cur.x; p1 += cur.y; p2 += cur.z; p3 += cur.w;
            float ig = sig_apx(p0);
            float fg = sig_apx(p1);
            float gg = tanh_apx(p2);
            float og = sig_apx(p3);
            c = fg * c + ig * gg;
            float h = og * tanh_apx(c);
            hsm[(t + 1) & 1][ul] = h;
            hout[(size_t)t * HID] = h;
        }
        __syncthreads();
    };

    const int STR = GATES / 4;   // float4 stride per t
    float4 r0 = make_float4(0.f, 0.f, 0.f, 0.f);
    float4 r1 = r0, r2 = r0, r3 = r0;
    if (q == 0) {
        r0 = __ldcs(pp + 0 * STR);
        r1 = __ldcs(pp + 1 * STR);
        r2 = __ldcs(pp + 2 * STR);
        r3 = __ldcs(pp + 3 * STR);
    }
    #pragma unroll 1
    for (int t = 0; t < TT; t += 4) {
        step(t + 0, r0); if (q == 0 && t + 4 < TT) r0 = __ldcs(pp + (size_t)(t + 4) * STR);
        step(t + 1, r1); if (q == 0 && t + 5 < TT) r1 = __ldcs(pp + (size_t)(t + 5) * STR);
        step(t + 2, r2); if (q == 0 && t + 6 < TT) r2 = __ldcs(pp + (size_t)(t + 6) * STR);
        step(t + 3, r3); if (q == 0 && t + 7 < TT) r3 = __ldcs(pp + (size_t)(t + 7) * STR);
    }
}

__global__ void __launch_bounds__(128, 1)
k_scan(const float* __restrict__ whh_rh, const float* __restrict__ whh_ra,
       const float* __restrict__ whh_lh, const float* __restrict__ whh_la) {
    __shared__ __align__(16) float hsm[2][64];
    int seg = blockIdx.x & 3;      // low bits: interleave heavy/light CTAs across SMs
    int b   = blockIdx.x >> 2;
    if (seg == 0)      scan_cta<64, 2, 0,   0  >(whh_rh, b, hsm);
    else if (seg == 1) scan_cta<32, 4, 256, 64 >(whh_ra, b, hsm);
    else if (seg == 2) scan_cta<64, 2, 384, 96 >(whh_lh, b, hsm);
    else               scan_cta<32, 4, 640, 160>(whh_la, b, hsm);
}

// ---------------------------------------------------------------------------
// K4: attention + FC.  1 CTA/sample, 1024 threads.
// out layout: [0 : 128*250) = logits, [128*250 : +128*512) = weights
// ---------------------------------------------------------------------------
__global__ void __launch_bounds__(1024)
k_att(const float* __restrict__ att_w, const float* __restrict__ fc_w,
      const float* __restrict__ fc_b, float* __restrict__ out) {
    __shared__ float sw[HID];
    __shared__ float sc[TT];
    __shared__ float red[32];
    __shared__ float ctxp[4][HID];
    __shared__ float ctx[HID];
    __shared__ float sval;
    int b = blockIdx.x, tid = threadIdx.x;
    int lane = tid & 31, wid = tid >> 5;
    const float* hsb = g_hs + (size_t)b * TT * HID;

    if (tid < HID) sw[tid] = att_w[tid];
    __syncthreads();

    // scores: one warp per t, 32 warps (coalesced h reads)
    for (int t = wid; t < TT; t += 32) {
        const float* hr = hsb + (size_t)t * HID;
        float s = 0.f;
        #pragma unroll
        for (int k = 0; k < 6; k++) s += sw[lane + 32 * k] * hr[lane + 32 * k];
        #pragma unroll
        for (int o = 16; o > 0; o >>= 1) s += __shfl_xor_sync(0xffffffffu, s, o);
        if (lane == 0) sc[t] = s;
    }
    __syncthreads();

    // softmax over T (threads 0..511)
    float v = (tid < TT) ? sc[tid] : -1e30f;
    float m = v;
    #pragma unroll
    for (int o = 16; o > 0; o >>= 1) m = fmaxf(m, __shfl_xor_sync(0xffffffffu, m, o));
    if (lane == 0) red[wid] = m;
    __syncthreads();
    if (tid == 0) {
        float mm = red[0];
        #pragma unroll
        for (int i = 1; i < 32; i++) mm = fmaxf(mm, red[i]);
        sval = mm;
    }
    __syncthreads();
    float e = (tid < TT) ? __expf(v - sval) : 0.f;
    float s = e;
    #pragma unroll
    for (int o = 16; o > 0; o >>= 1) s += __shfl_xor_sync(0xffffffffu, s, o);
    if (lane == 0) red[wid] = s;
    __syncthreads();
    if (tid == 0) {
        float ss = 0.f;
        #pragma unroll
        for (int i = 0; i < 32; i++) ss += red[i];
        sval = ss;
    }
    __syncthreads();
    if (tid < TT) {
        float wgt = e * (1.f / sval);
        sc[tid] = wgt;
        out[BB * NCLS + b * TT + tid] = wgt;
    }
    __syncthreads();

    // context: four t-quarters in parallel (threads 0..767)
    if (tid < 4 * HID) {
        int grp = tid / HID;
        int k = tid - grp * HID;
        int tb = grp * (TT / 4);
        float acc = 0.f;
        #pragma unroll 8
        for (int t = tb; t < tb + TT / 4; t++) acc += sc[t] * hsb[(size_t)t * HID + k];
        ctxp[grp][k] = acc;
    }
    __syncthreads();
    if (tid < HID) ctx[tid] = ctxp[0][tid] + ctxp[1][tid] + ctxp[2][tid] + ctxp[3][tid];
    __syncthreads();

    // FC: 4 threads per class (k-split 48 each, combined via two shfls)
    {
        int cls = tid >> 2, part = tid & 3;
        bool valid = (cls < NCLS);
        const float* wr = fc_w + (size_t)(valid ? cls : 0) * HID + part * 48;
        const float* cx = ctx + part * 48;
        float acc = 0.f;
        #pragma unroll 8
        for (int k = 0; k < 48; k++) acc += cx[k] * wr[k];
        acc += __shfl_xor_sync(0xffffffffu, acc, 1);
        acc += __shfl_xor_sync(0xffffffffu, acc, 2);
        if (valid && part == 0) out[b * NCLS + cls] = acc + fc_b[cls];
    }
}

// ---------------------------------------------------------------------------
extern "C" void kernel_launch(void* const* d_in, const int* in_sizes, int n_in,
                              void* d_out, int out_size) {
    const float* x      = (const float*)d_in[0];
    const float* wih_rh = (const float*)d_in[1];
    const float* whh_rh = (const float*)d_in[2];
    const float* bih_rh = (const float*)d_in[3];
    const float* bhh_rh = (const float*)d_in[4];
    const float* wih_ra = (const float*)d_in[5];
    const float* whh_ra = (const float*)d_in[6];
    const float* bih_ra = (const float*)d_in[7];
    const float* bhh_ra = (const float*)d_in[8];
    const float* wih_lh = (const float*)d_in[9];
    const float* whh_lh = (const float*)d_in[10];
    const float* bih_lh = (const float*)d_in[11];
    const float* bhh_lh = (const float*)d_in[12];
    const float* wih_la = (const float*)d_in[13];
    const float* whh_la = (const float*)d_in[14];
    const float* bih_la = (const float*)d_in[15];
    const float* bhh_la = (const float*)d_in[16];
    const float* att_w  = (const float*)d_in[17];
    const float* fc_w   = (const float*)d_in[18];
    const float* fc_b   = (const float*)d_in[19];
    float* out = (float*)d_out;

    k_feat<<<(BB * TT + 255) / 256, 256>>>(x);
    k_ingemm<<<BB * 4, 768>>>(wih_rh, bih_rh, bhh_rh,
                              wih_ra, bih_ra, bhh_ra,
                              wih_lh, bih_lh, bhh_lh,
                              wih_la, bih_la, bhh_la);
    k_scan<<<BB * 4, 128>>>(whh_rh, whh_ra, whh_lh, whh_la);
    k_att<<<BB, 1024>>>(att_w, fc_w, fc_b, out);
}

// round 9
// speedup vs baseline: 1.2397x; 1.2397x over previous
#include <cuda_runtime.h>
#include <cuda_bf16.h>

#define BB    128
#define TT    512
#define FEAT  96
#define GATES 768
#define HID   192
#define NCLS  250

// scratch (device globals; allocations are forbidden)
__device__ __align__(16) float g_pre [BB * TT * GATES];    // 201 MB (streamed, evict-first)
__device__ __align__(16) float g_hs  [BB * TT * HID];      // 50 MB  (kept L2-resident)

// ---------------- packed f32x2 helpers ----------------
__device__ __forceinline__ unsigned long long pack2(float x, float y) {
    unsigned long long u;
    asm("mov.b64 %0, {%1, %2};" : "=l"(u) : "f"(x), "f"(y));
    return u;
}
__device__ __forceinline__ unsigned long long ffma2(unsigned long long a,
                                                    unsigned long long b,
                                                    unsigned long long c) {
    unsigned long long d;
    asm("fma.rn.f32x2 %0, %1, %2, %3;" : "=l"(d) : "l"(a), "l"(b), "l"(c));
    return d;
}
__device__ __forceinline__ float pairsum(unsigned long long a) {
    float x, y;
    asm("mov.b64 {%0, %1}, %2;" : "=f"(x), "=f"(y) : "l"(a));
    return x + y;
}
__device__ __forceinline__ float tanh_apx(float x) {
    float y;
    asm("tanh.approx.f32 %0, %1;" : "=f"(y) : "f"(x));
    return y;
}
__device__ __forceinline__ float sig_apx(float x) {
    return fmaf(tanh_apx(0.5f * x), 0.5f, 0.5f);
}

// ---------------------------------------------------------------------------
// K2: fused feature-prep + input GEMM.
// Block = (sample b, 128-t tile).  Stage the 128 raw x rows (136KB,
// contiguous -> float4 coalesced) in smem, compute features in-block
// (layout per t: [0:42] rh, [42:48] ra, [48:90] lh, [90:96] la), then the
// 768-thread GEMM: pre[b][t][g] = (bih+bhh) + wih_row . feat, stores .cs.
// ---------------------------------------------------------------------------
#define XROW   266
#define XTILE  (128 * XROW)                 // 34048 floats
#define SMEM_INGEMM ((XTILE + 128 * FEAT) * 4)   // 185,344 bytes

__global__ void __launch_bounds__(768)
k_ingemm(const float* __restrict__ x,
         const float* __restrict__ wih_rh, const float* __restrict__ bih_rh, const float* __restrict__ bhh_rh,
         const float* __restrict__ wih_ra, const float* __restrict__ bih_ra, const float* __restrict__ bhh_ra,
         const float* __restrict__ wih_lh, const float* __restrict__ bih_lh, const float* __restrict__ bhh_lh,
         const float* __restrict__ wih_la, const float* __restrict__ bih_la, const float* __restrict__ bhh_la) {
    extern __shared__ __align__(16) float smem[];
    float* xs = smem;                 // [128][266]
    float* fs = smem + XTILE;         // [128][96], 16B aligned (XTILE*4 % 16 == 0)

    int b  = blockIdx.x >> 2;
    int t0 = (blockIdx.x & 3) << 7;
    int g  = threadIdx.x;

    // stage x rows: 136KB contiguous, float4 coalesced
    {
        const float4* src4 = (const float4*)(x + ((size_t)b * TT + t0) * XROW);
        float4* dst4 = (float4*)xs;
        for (int i = g; i < XTILE / 4; i += 768) dst4[i] = src4[i];
    }

    // weight/bias setup (independent of smem)
    int r, F, k0, H;
    const float *wih, *bih, *bhh;
    if (g < 256)      { r = g;       F = 42; k0 = 0;  H = 64; wih = wih_rh; bih = bih_rh; bhh = bhh_rh; }
    else if (g < 384) { r = g - 256; F = 6;  k0 = 42; H = 32; wih = wih_ra; bih = bih_ra; bhh = bhh_ra; }
    else if (g < 640) { r = g - 384; F = 42; k0 = 48; H = 64; wih = wih_lh; bih = bih_lh; bhh = bhh_lh; }
    else              { r = g - 640; F = 6;  k0 = 90; H = 32; wih = wih_la; bih = bih_la; bhh = bhh_la; }
    int ul = r >> 2, gate = r & 3;
    int row = gate * H + ul;
    float bias = bih[row] + bhh[row];
    float* po = g_pre + ((size_t)b * TT + t0) * GATES + g;

    unsigned long long w[21];
    if (F == 42) {
        const float* wr = wih + row * 42;
        #pragma unroll
        for (int i = 0; i < 21; i++) {
            float2 v = *(const float2*)(wr + 2 * i);
            w[i] = pack2(v.x, v.y);
        }
    } else {
        const float* wr = wih + row * 6;
        #pragma unroll
        for (int i = 0; i < 3; i++) {
            float2 v = *(const float2*)(wr + 2 * i);
            w[i] = pack2(v.x, v.y);
        }
    }
    __syncthreads();

    // feature computation: one thread per t (threads 0..127)
    if (g < 128) {
        const float* rowx = xs + g * XROW;
        float* out = fs + g * FEAT;
        // right hand: points 112..132 (floats 224..265), ref pt10 (20,21)
        {
            float rx = rowx[20], ry = rowx[21];
            float mnx = 1e30f, mxx = -1e30f, mny = 1e30f, mxy = -1e30f;
            #pragma unroll
            for (int p = 0; p < 21; p++) {
                float px = rowx[224 + 2 * p], py = rowx[225 + 2 * p];
                mnx = fminf(mnx, px); mxx = fmaxf(mxx, px);
                mny = fminf(mny, py); mxy = fmaxf(mxy, py);
            }
            float s = fmaxf(mxx - mnx, mxy - mny);
            s = (s == 0.f) ? 1.f : s;
            float inv = 1.f / s;
            #pragma unroll
            for (int p = 0; p < 21; p++) {
                out[2 * p]     = (rowx[224 + 2 * p] - rx) * inv;
                out[2 * p + 1] = (rowx[225 + 2 * p] - ry) * inv;
            }
        }
        // right arm: points 6,8,10 (12,16,20), ref pt0
        {
            float cx = rowx[0], cy = rowx[1];
            float x0 = rowx[12], y0 = rowx[13];
            float x1 = rowx[16], y1 = rowx[17];
            float x2 = rowx[20], y2 = rowx[21];
            float wd = fmaxf(fmaxf(x0, x1), x2) - fminf(fminf(x0, x1), x2);
            float ht = fmaxf(fmaxf(y0, y1), y2) - fminf(fminf(y0, y1), y2);
            float s = fmaxf(wd, ht); s = (s == 0.f) ? 1.f : s;
            float inv = 1.f / s;
            out[42] = (x0 - cx) * inv; out[43] = (y0 - cy) * inv;
            out[44] = (x1 - cx) * inv; out[45] = (y1 - cy) * inv;
            out[46] = (x2 - cx) * inv; out[47] = (y2 - cy) * inv;
        }
        // left hand: points 91..111 (floats 182..223), ref pt9 (18,19)
        {
            float rx = rowx[18], ry = rowx[19];
            float mnx = 1e30f, mxx = -1e30f, mny = 1e30f, mxy = -1e30f;
            #pragma unroll
            for (int p = 0; p < 21; p++) {
                float px = rowx[182 + 2 * p], py = rowx[183 + 2 * p];
                mnx = fminf(mnx, px); mxx = fmaxf(mxx, px);
                mny = fminf(mny, py); mxy = fmaxf(mxy, py);
            }
            float s = fmaxf(mxx - mnx, mxy - mny);
            s = (s == 0.f) ? 1.f : s;
            float inv = 1.f / s;
            #pragma unroll
            for (int p = 0; p < 21; p++) {
                out[48 + 2 * p] = (rowx[182 + 2 * p] - rx) * inv;
                out[49 + 2 * p] = (rowx[183 + 2 * p] - ry) * inv;
            }
        }
        // left arm: points 5,7,9 (10,14,18), ref pt0
        {
            float cx = rowx[0], cy = rowx[1];
            float x0 = rowx[10], y0 = rowx[11];
            float x1 = rowx[14], y1 = rowx[15];
            float x2 = rowx[18], y2 = rowx[19];
            float wd = fmaxf(fmaxf(x0, x1), x2) - fminf(fminf(x0, x1), x2);
            float ht = fmaxf(fmaxf(y0, y1), y2) - fminf(fminf(y0, y1), y2);
            float s = fmaxf(wd, ht); s = (s == 0.f) ? 1.f : s;
            float inv = 1.f / s;
            out[90] = (x0 - cx) * inv; out[91] = (y0 - cy) * inv;
            out[92] = (x1 - cx) * inv; out[93] = (y1 - cy) * inv;
            out[94] = (x2 - cx) * inv; out[95] = (y2 - cy) * inv;
        }
    }
    __syncthreads();

    // GEMM over the 128-t tile
    if (F == 42) {
        #pragma unroll 2
        for (int t = 0; t < 128; t++) {
            const float* fp = fs + t * FEAT + k0;   // 16B aligned (k0 = 0 or 48)
            unsigned long long aA = 0ull, aB = 0ull;
            #pragma unroll
            for (int i = 0; i < 10; i++) {
                ulonglong2 q = *(const ulonglong2*)(fp + 4 * i);
                aA = ffma2(w[2 * i],     q.x, aA);
                aB = ffma2(w[2 * i + 1], q.y, aB);
            }
            unsigned long long tail = *(const unsigned long long*)(fp + 40);
            aA = ffma2(w[20], tail, aA);
            __stcs(po + (size_t)t * GATES, bias + pairsum(aA) + pairsum(aB));
        }
    } else {
        #pragma unroll 2
        for (int t = 0; t < 128; t++) {
            const unsigned long long* f2 = (const unsigned long long*)(fs + t * FEAT + k0);
            unsigned long long a = 0ull;
            #pragma unroll
            for (int i = 0; i < 3; i++) a = ffma2(w[i], f2[i], a);
            __stcs(po + (size_t)t * GATES, bias + pairsum(a));
        }
    }
}

// ---------------------------------------------------------------------------
// K3: recurrent scan (R7 structure).  1 CTA/sample, 384 threads = 2 per
// hidden unit.  Per-segment named barriers; weights in registers; h double-
// buffered in smem; depth-4 register prefetch ring on pre (.cs loads).
// Activations computed BRANCH-FREE on all lanes (after bfly both halves hold
// identical full gate sums); only the stores are predicated.
// ---------------------------------------------------------------------------
template<int BARID, int BARCNT>
__device__ __forceinline__ void seg_bar() {
    asm volatile("bar.sync %0, %1;" :: "n"(BARID), "n"(BARCNT) : "memory");
}

template<int H, int HB, int PB, int BARID, int BARCNT>
__device__ __forceinline__ void scan_seg(const float* __restrict__ whh, int b,
                                         int ul, int half, int u,
                                         float (*hsm)[HID]) {
    constexpr int HW = H / 2;    // floats per half-dot
    constexpr int NH = HW / 2;   // u64 per gate
    constexpr int NQ = NH / 2;   // ulonglong2 per gate
    unsigned long long w[4 * NH];
    #pragma unroll
    for (int gI = 0; gI < 4; gI++) {
        const float* rw = whh + (gI * H + ul) * H + half * HW;
        #pragma unroll
        for (int i = 0; i < NH; i++) {
            float2 v = *(const float2*)(rw + 2 * i);
            w[gI * NH + i] = pack2(v.x, v.y);
        }
    }
    const float2* pp = (const float2*)(g_pre + (size_t)b * TT * GATES + PB + ul * 4 + half * 2);
    float* hout = g_hs + (size_t)b * TT * HID + u;
    float c = 0.f;
    bool store = (half == 0);

    auto step = [&](int t, float2 cur) {
        const ulonglong2* hv = (const ulonglong2*)&hsm[t & 1][HB + half * HW];
        unsigned long long a0 = 0ull, a1 = 0ull, a2 = 0ull, a3 = 0ull;
        #pragma unroll
        for (int i = 0; i < NQ; i++) {
            ulonglong2 q = hv[i];
            a0 = ffma2(w[0 * NH + 2 * i],     q.x, a0);
            a0 = ffma2(w[0 * NH + 2 * i + 1], q.y, a0);
            a1 = ffma2(w[1 * NH + 2 * i],     q.x, a1);
            a1 = ffma2(w[1 * NH + 2 * i + 1], q.y, a1);
            a2 = ffma2(w[2 * NH + 2 * i],     q.x, a2);
            a2 = ffma2(w[2 * NH + 2 * i + 1], q.y, a2);
            a3 = ffma2(w[3 * NH + 2 * i],     q.x, a3);
            a3 = ffma2(w[3 * NH + 2 * i + 1], q.y, a3);
        }
        float p0 = pairsum(a0), p1 = pairsum(a1), p2 = pairsum(a2), p3 = pairsum(a3);
        if (half == 0) { p0 += cur.x; p1 += cur.y; }
        else           { p2 += cur.x; p3 += cur.y; }
        p0 += __shfl_xor_sync(0xffffffffu, p0, 1);
        p1 += __shfl_xor_sync(0xffffffffu, p1, 1);
        p2 += __shfl_xor_sync(0xffffffffu, p2, 1);
        p3 += __shfl_xor_sync(0xffffffffu, p3, 1);
        // branch-free: both halves now hold identical full sums
        float ig = sig_apx(p0);
        float fg = sig_apx(p1);
        float gg = tanh_apx(p2);
        float og = sig_apx(p3);
        c = fg * c + ig * gg;
        float h = og * tanh_apx(c);
        if (store) {
            hsm[(t + 1) & 1][u] = h;
            hout[(size_t)t * HID] = h;
        }
        seg_bar<BARID, BARCNT>();
    };

    const int STR = GATES / 2;   // float2 stride per t
    float2 r0 = __ldcs(pp + 0 * STR);
    float2 r1 = __ldcs(pp + 1 * STR);
    float2 r2 = __ldcs(pp + 2 * STR);
    float2 r3 = __ldcs(pp + 3 * STR);
    #pragma unroll 1
    for (int t = 0; t < TT; t += 4) {
        step(t + 0, r0); if (t + 4 < TT) r0 = __ldcs(pp + (size_t)(t + 4) * STR);
        step(t + 1, r1); if (t + 5 < TT) r1 = __ldcs(pp + (size_t)(t + 5) * STR);
        step(t + 2, r2); if (t + 6 < TT) r2 = __ldcs(pp + (size_t)(t + 6) * STR);
        step(t + 3, r3); if (t + 7 < TT) r3 = __ldcs(pp + (size_t)(t + 7) * STR);
    }
}

__global__ void __launch_bounds__(384, 1)
k_scan(const float* __restrict__ whh_rh, const float* __restrict__ whh_ra,
       const float* __restrict__ whh_lh, const float* __restrict__ whh_la) {
    __shared__ __align__(16) float hsm[2][HID];
    int b = blockIdx.x, tid = threadIdx.x;
    int u = tid >> 1, half = tid & 1;
    if (tid < HID) hsm[0][tid] = 0.f;
    __syncthreads();
    // warp ranges per segment: rh w0-3, ra w4-5, lh w6-9, la w10-11
    if (u < 64)       scan_seg<64, 0,   0,   1, 128>(whh_rh, b, u,       half, u, hsm);
    else if (u < 96)  scan_seg<32, 64,  256, 2, 64 >(whh_ra, b, u - 64,  half, u, hsm);
    else if (u < 160) scan_seg<64, 96,  384, 3, 128>(whh_lh, b, u - 96,  half, u, hsm);
    else              scan_seg<32, 160, 640, 4, 64 >(whh_la, b, u - 160, half, u, hsm);
}

// ---------------------------------------------------------------------------
// K4: attention + FC.  1 CTA/sample, 1024 threads.
// out layout: [0 : 128*250) = logits, [128*250 : +128*512) = weights
// ---------------------------------------------------------------------------
__global__ void __launch_bounds__(1024)
k_att(const float* __restrict__ att_w, const float* __restrict__ fc_w,
      const float* __restrict__ fc_b, float* __restrict__ out) {
    __shared__ float sw[HID];
    __shared__ float sc[TT];
    __shared__ float red[32];
    __shared__ float ctxp[4][HID];
    __shared__ float ctx[HID];
    __shared__ float sval;
    int b = blockIdx.x, tid = threadIdx.x;
    int lane = tid & 31, wid = tid >> 5;
    const float* hsb = g_hs + (size_t)b * TT * HID;

    if (tid < HID) sw[tid] = att_w[tid];
    __syncthreads();

    // scores: one warp per t, 32 warps (coalesced h reads)
    for (int t = wid; t < TT; t += 32) {
        const float* hr = hsb + (size_t)t * HID;
        float s = 0.f;
        #pragma unroll
        for (int k = 0; k < 6; k++) s += sw[lane + 32 * k] * hr[lane + 32 * k];
        #pragma unroll
        for (int o = 16; o > 0; o >>= 1) s += __shfl_xor_sync(0xffffffffu, s, o);
        if (lane == 0) sc[t] = s;
    }
    __syncthreads();

    // softmax over T (threads 0..511)
    float v = (tid < TT) ? sc[tid] : -1e30f;
    float m = v;
    #pragma unroll
    for (int o = 16; o > 0; o >>= 1) m = fmaxf(m, __shfl_xor_sync(0xffffffffu, m, o));
    if (lane == 0) red[wid] = m;
    __syncthreads();
    if (tid == 0) {
        float mm = red[0];
        #pragma unroll
        for (int i = 1; i < 32; i++) mm = fmaxf(mm, red[i]);
        sval = mm;
    }
    __syncthreads();
    float e = (tid < TT) ? __expf(v - sval) : 0.f;
    float s = e;
    #pragma unroll
    for (int o = 16; o > 0; o >>= 1) s += __shfl_xor_sync(0xffffffffu, s, o);
    if (lane == 0) red[wid] = s;
    __syncthreads();
    if (tid == 0) {
        float ss = 0.f;
        #pragma unroll
        for (int i = 0; i < 32; i++) ss += red[i];
        sval = ss;
    }
    __syncthreads();
    if (tid < TT) {
        float wgt = e * (1.f / sval);
        sc[tid] = wgt;
        out[BB * NCLS + b * TT + tid] = wgt;
    }
    __syncthreads();

    // context: four t-quarters in parallel (threads 0..767)
    if (tid < 4 * HID) {
        int grp = tid / HID;
        int k = tid - grp * HID;
        int tb = grp * (TT / 4);
        float acc = 0.f;
        #pragma unroll 8
        for (int t = tb; t < tb + TT / 4; t++) acc += sc[t] * hsb[(size_t)t * HID + k];
        ctxp[grp][k] = acc;
    }
    __syncthreads();
    if (tid < HID) ctx[tid] = ctxp[0][tid] + ctxp[1][tid] + ctxp[2][tid] + ctxp[3][tid];
    __syncthreads();

    // FC: 4 threads per class (k-split 48 each, combined via two shfls)
    {
        int cls = tid >> 2, part = tid & 3;
        bool valid = (cls < NCLS);
        const float* wr = fc_w + (size_t)(valid ? cls : 0) * HID + part * 48;
        const float* cx = ctx + part * 48;
        float acc = 0.f;
        #pragma unroll 8
        for (int k = 0; k < 48; k++) acc += cx[k] * wr[k];
        acc += __shfl_xor_sync(0xffffffffu, acc, 1);
        acc += __shfl_xor_sync(0xffffffffu, acc, 2);
        if (valid && part == 0) out[b * NCLS + cls] = acc + fc_b[cls];
    }
}

// ---------------------------------------------------------------------------
extern "C" void kernel_launch(void* const* d_in, const int* in_sizes, int n_in,
                              void* d_out, int out_size) {
    const float* x      = (const float*)d_in[0];
    const float* wih_rh = (const float*)d_in[1];
    const float* whh_rh = (const float*)d_in[2];
    const float* bih_rh = (const float*)d_in[3];
    const float* bhh_rh = (const float*)d_in[4];
    const float* wih_ra = (const float*)d_in[5];
    const float* whh_ra = (const float*)d_in[6];
    const float* bih_ra = (const float*)d_in[7];
    const float* bhh_ra = (const float*)d_in[8];
    const float* wih_lh = (const float*)d_in[9];
    const float* whh_lh = (const float*)d_in[10];
    const float* bih_lh = (const float*)d_in[11];
    const float* bhh_lh = (const float*)d_in[12];
    const float* wih_la = (const float*)d_in[13];
    const float* whh_la = (const float*)d_in[14];
    const float* bih_la = (const float*)d_in[15];
    const float* bhh_la = (const float*)d_in[16];
    const float* att_w  = (const float*)d_in[17];
    const float* fc_w   = (const float*)d_in[18];
    const float* fc_b   = (const float*)d_in[19];
    float* out = (float*)d_out;

    static int smem_set = 0;
    if (!smem_set) {
        cudaFuncSetAttribute(k_ingemm, cudaFuncAttributeMaxDynamicSharedMemorySize,
                             SMEM_INGEMM);
        smem_set = 1;
    }

    k_ingemm<<<BB * 4, 768, SMEM_INGEMM>>>(x,
                              wih_rh, bih_rh, bhh_rh,
                              wih_ra, bih_ra, bhh_ra,
                              wih_lh, bih_lh, bhh_lh,
                              wih_la, bih_la, bhh_la);
    k_scan<<<BB, 384>>>(whh_rh, whh_ra, whh_lh, whh_la);
    k_att<<<BB, 1024>>>(att_w, fc_w, fc_b, out);
}

// round 10
// speedup vs baseline: 1.2753x; 1.0287x over previous
#include <cuda_runtime.h>
#include <cuda_bf16.h>

#define BB    128
#define TT    512
#define FEAT  96
#define GATES 768
#define HID   192
#define NCLS  250

// scratch (device globals; allocations are forbidden)
__device__ __align__(16) float g_feat[BB * TT * FEAT];     // 25 MB
__device__ __align__(16) float g_pre [BB * TT * GATES];    // 201 MB (streamed, evict-first)
__device__ __align__(16) float g_hs  [BB * TT * HID];      // 50 MB  (kept L2-resident)

// ---------------- packed f32x2 helpers ----------------
__device__ __forceinline__ unsigned long long pack2(float x, float y) {
    unsigned long long u;
    asm("mov.b64 %0, {%1, %2};" : "=l"(u) : "f"(x), "f"(y));
    return u;
}
__device__ __forceinline__ unsigned long long ffma2(unsigned long long a,
                                                    unsigned long long b,
                                                    unsigned long long c) {
    unsigned long long d;
    asm("fma.rn.f32x2 %0, %1, %2, %3;" : "=l"(d) : "l"(a), "l"(b), "l"(c));
    return d;
}
__device__ __forceinline__ float pairsum(unsigned long long a) {
    float x, y;
    asm("mov.b64 {%0, %1}, %2;" : "=f"(x), "=f"(y) : "l"(a));
    return x + y;
}
__device__ __forceinline__ float tanh_apx(float x) {
    float y;
    asm("tanh.approx.f32 %0, %1;" : "=f"(y) : "f"(x));
    return y;
}
__device__ __forceinline__ float sig_apx(float x) {
    return fmaf(tanh_apx(0.5f * x), 0.5f, 0.5f);
}

// ---------------------------------------------------------------------------
// K1: feature prep. One thread per (b,t).
// layout per (b,t): [0:42] right hand, [42:48] right arm, [48:90] left hand,
//                   [90:96] left arm   (matches LSTM order rh,ra,lh,la)
// ---------------------------------------------------------------------------
__global__ void __launch_bounds__(256) k_feat(const float* __restrict__ x) {
    int idx = blockIdx.x * 256 + threadIdx.x;
    if (idx >= BB * TT) return;
    const float* row = x + (size_t)idx * 266;
    float* out = g_feat + (size_t)idx * FEAT;

    // right hand: points 112..132 (floats 224..265), ref point 10 (floats 20,21)
    {
        float rx = row[20], ry = row[21];
        float mnx = 1e30f, mxx = -1e30f, mny = 1e30f, mxy = -1e30f;
        #pragma unroll
        for (int p = 0; p < 21; p++) {
            float px = row[224 + 2 * p], py = row[225 + 2 * p];
            mnx = fminf(mnx, px); mxx = fmaxf(mxx, px);
            mny = fminf(mny, py); mxy = fmaxf(mxy, py);
        }
        float s = fmaxf(mxx - mnx, mxy - mny);
        s = (s == 0.f) ? 1.f : s;
        float inv = 1.f / s;
        #pragma unroll
        for (int p = 0; p < 21; p++) {
            out[2 * p]     = (row[224 + 2 * p] - rx) * inv;
            out[2 * p + 1] = (row[225 + 2 * p] - ry) * inv;
        }
    }
    // right arm: points 6,8,10 (floats 12,16,20), ref point 0
    {
        float cx = row[0], cy = row[1];
        float x0 = row[12], y0 = row[13];
        float x1 = row[16], y1 = row[17];
        float x2 = row[20], y2 = row[21];
        float w = fmaxf(fmaxf(x0, x1), x2) - fminf(fminf(x0, x1), x2);
        float h = fmaxf(fmaxf(y0, y1), y2) - fminf(fminf(y0, y1), y2);
        float s = fmaxf(w, h); s = (s == 0.f) ? 1.f : s;
        float inv = 1.f / s;
        out[42] = (x0 - cx) * inv; out[43] = (y0 - cy) * inv;
        out[44] = (x1 - cx) * inv; out[45] = (y1 - cy) * inv;
        out[46] = (x2 - cx) * inv; out[47] = (y2 - cy) * inv;
    }
    // left hand: points 91..111 (floats 182..223), ref point 9 (floats 18,19)
    {
        float rx = row[18], ry = row[19];
        float mnx = 1e30f, mxx = -1e30f, mny = 1e30f, mxy = -1e30f;
        #pragma unroll
        for (int p = 0; p < 21; p++) {
            float px = row[182 + 2 * p], py = row[183 + 2 * p];
            mnx = fminf(mnx, px); mxx = fmaxf(mxx, px);
            mny = fminf(mny, py); mxy = fmaxf(mxy, py);
        }
        float s = fmaxf(mxx - mnx, mxy - mny);
        s = (s == 0.f) ? 1.f : s;
        float inv = 1.f / s;
        #pragma unroll
        for (int p = 0; p < 21; p++) {
            out[48 + 2 * p] = (row[182 + 2 * p] - rx) * inv;
            out[49 + 2 * p] = (row[183 + 2 * p] - ry) * inv;
        }
    }
    // left arm: points 5,7,9 (floats 10,14,18), ref point 0
    {
        float cx = row[0], cy = row[1];
        float x0 = row[10], y0 = row[11];
        float x1 = row[14], y1 = row[15];
        float x2 = row[18], y2 = row[19];
        float w = fmaxf(fmaxf(x0, x1), x2) - fminf(fminf(x0, x1), x2);
        float h = fmaxf(fmaxf(y0, y1), y2) - fminf(fminf(y0, y1), y2);
        float s = fmaxf(w, h); s = (s == 0.f) ? 1.f : s;
        float inv = 1.f / s;
        out[90] = (x0 - cx) * inv; out[91] = (y0 - cy) * inv;
        out[92] = (x1 - cx) * inv; out[93] = (y1 - cy) * inv;
        out[94] = (x2 - cx) * inv; out[95] = (y2 - cy) * inv;
    }
}

// ---------------------------------------------------------------------------
// K2: input GEMM.  pre[b][t][g] = (bih+bhh) + wih_row . feat
// 768 threads = one output column each (warp stores 128B coalesced).
// Inner loop processes TWO t-values (t, t+64) with independent accumulators
// -> halves exposed FFMA-chain latency per LDS batch.
// pre stored with .cs so the 201MB stream doesn't evict g_hs from L2.
// ---------------------------------------------------------------------------
__global__ void __launch_bounds__(768)
k_ingemm(const float* __restrict__ wih_rh, const float* __restrict__ bih_rh, const float* __restrict__ bhh_rh,
         const float* __restrict__ wih_ra, const float* __restrict__ bih_ra, const float* __restrict__ bhh_ra,
         const float* __restrict__ wih_lh, const float* __restrict__ bih_lh, const float* __restrict__ bhh_lh,
         const float* __restrict__ wih_la, const float* __restrict__ bih_la, const float* __restrict__ bhh_la) {
    __shared__ __align__(16) float fs[128 * FEAT];   // 48 KB
    int b  = blockIdx.x >> 2;
    int t0 = (blockIdx.x & 3) << 7;
    int g  = threadIdx.x;

    const float4* src4 = (const float4*)(g_feat + ((size_t)b * TT + t0) * FEAT);
    float4* dst4 = (float4*)fs;
    for (int i = g; i < 128 * FEAT / 4; i += 768) dst4[i] = src4[i];

    int r, F, k0, H;
    const float *wih, *bih, *bhh;
    if (g < 256)      { r = g;       F = 42; k0 = 0;  H = 64; wih = wih_rh; bih = bih_rh; bhh = bhh_rh; }
    else if (g < 384) { r = g - 256; F = 6;  k0 = 42; H = 32; wih = wih_ra; bih = bih_ra; bhh = bhh_ra; }
    else if (g < 640) { r = g - 384; F = 42; k0 = 48; H = 64; wih = wih_lh; bih = bih_lh; bhh = bhh_lh; }
    else              { r = g - 640; F = 6;  k0 = 90; H = 32; wih = wih_la; bih = bih_la; bhh = bhh_la; }
    int ul = r >> 2, gate = r & 3;
    int row = gate * H + ul;
    float bias = bih[row] + bhh[row];
    float* po = g_pre + ((size_t)b * TT + t0) * GATES + g;
    __syncthreads();

    if (F == 42) {
        unsigned long long w[21];
        const float* wr = wih + row * 42;
        #pragma unroll
        for (int i = 0; i < 21; i++) {
            float2 v = *(const float2*)(wr + 2 * i);
            w[i] = pack2(v.x, v.y);
        }
        #pragma unroll 1
        for (int t = 0; t < 64; t++) {
            const float* fpA = fs + t * FEAT + k0;          // 16B aligned
            const float* fpB = fs + (t + 64) * FEAT + k0;
            unsigned long long a0 = 0ull, a1 = 0ull, b0 = 0ull, b1 = 0ull;
            #pragma unroll
            for (int i = 0; i < 10; i++) {
                ulonglong2 qA = *(const ulonglong2*)(fpA + 4 * i);
                ulonglong2 qB = *(const ulonglong2*)(fpB + 4 * i);
                a0 = ffma2(w[2 * i],     qA.x, a0);
                a1 = ffma2(w[2 * i + 1], qA.y, a1);
                b0 = ffma2(w[2 * i],     qB.x, b0);
                b1 = ffma2(w[2 * i + 1], qB.y, b1);
            }
            unsigned long long tA = *(const unsigned long long*)(fpA + 40);
            unsigned long long tB = *(const unsigned long long*)(fpB + 40);
            a0 = ffma2(w[20], tA, a0);
            b0 = ffma2(w[20], tB, b0);
            __stcs(po + (size_t)t * GATES,        bias + pairsum(a0) + pairsum(a1));
            __stcs(po + (size_t)(t + 64) * GATES, bias + pairsum(b0) + pairsum(b1));
        }
    } else {
        unsigned long long w[3];
        const float* wr = wih + row * 6;
        #pragma unroll
        for (int i = 0; i < 3; i++) {
            float2 v = *(const float2*)(wr + 2 * i);
            w[i] = pack2(v.x, v.y);
        }
        #pragma unroll 1
        for (int t = 0; t < 64; t++) {
            const unsigned long long* fA = (const unsigned long long*)(fs + t * FEAT + k0);
            const unsigned long long* fB = (const unsigned long long*)(fs + (t + 64) * FEAT + k0);
            unsigned long long a = 0ull, bacc = 0ull;
            #pragma unroll
            for (int i = 0; i < 3; i++) {
                a    = ffma2(w[i], fA[i], a);
                bacc = ffma2(w[i], fB[i], bacc);
            }
            __stcs(po + (size_t)t * GATES,        bias + pairsum(a));
            __stcs(po + (size_t)(t + 64) * GATES, bias + pairsum(bacc));
        }
    }
}

// ---------------------------------------------------------------------------
// K3: recurrent scan.  1 CTA/sample, 384 threads = 2 per hidden unit.
// Per-segment named barriers; weights in registers; h double-buffered in
// smem; depth-4 register prefetch ring on pre (.cs loads).
// Activations BRANCH-FREE on all lanes (after bfly both halves hold identical
// full gate sums); only the stores are predicated.
// ---------------------------------------------------------------------------
template<int BARID, int BARCNT>
__device__ __forceinline__ void seg_bar() {
    asm volatile("bar.sync %0, %1;" :: "n"(BARID), "n"(BARCNT) : "memory");
}

template<int H, int HB, int PB, int BARID, int BARCNT>
__device__ __forceinline__ void scan_seg(const float* __restrict__ whh, int b,
                                         int ul, int half, int u,
                                         float (*hsm)[HID]) {
    constexpr int HW = H / 2;    // floats per half-dot
    constexpr int NH = HW / 2;   // u64 per gate
    constexpr int NQ = NH / 2;   // ulonglong2 per gate
    unsigned long long w[4 * NH];
    #pragma unroll
    for (int gI = 0; gI < 4; gI++) {
        const float* rw = whh + (gI * H + ul) * H + half * HW;
        #pragma unroll
        for (int i = 0; i < NH; i++) {
            float2 v = *(const float2*)(rw + 2 * i);
            w[gI * NH + i] = pack2(v.x, v.y);
        }
    }
    const float2* pp = (const float2*)(g_pre + (size_t)b * TT * GATES + PB + ul * 4 + half * 2);
    float* hout = g_hs + (size_t)b * TT * HID + u;
    float c = 0.f;
    bool store = (half == 0);

    auto step = [&](int t, float2 cur) {
        const ulonglong2* hv = (const ulonglong2*)&hsm[t & 1][HB + half * HW];
        unsigned long long a0 = 0ull, a1 = 0ull, a2 = 0ull, a3 = 0ull;
        #pragma unroll
        for (int i = 0; i < NQ; i++) {
            ulonglong2 q = hv[i];
            a0 = ffma2(w[0 * NH + 2 * i],     q.x, a0);
            a0 = ffma2(w[0 * NH + 2 * i + 1], q.y, a0);
            a1 = ffma2(w[1 * NH + 2 * i],     q.x, a1);
            a1 = ffma2(w[1 * NH + 2 * i + 1], q.y, a1);
            a2 = ffma2(w[2 * NH + 2 * i],     q.x, a2);
            a2 = ffma2(w[2 * NH + 2 * i + 1], q.y, a2);
            a3 = ffma2(w[3 * NH + 2 * i],     q.x, a3);
            a3 = ffma2(w[3 * NH + 2 * i + 1], q.y, a3);
        }
        float p0 = pairsum(a0), p1 = pairsum(a1), p2 = pairsum(a2), p3 = pairsum(a3);
        if (half == 0) { p0 += cur.x; p1 += cur.y; }
        else           { p2 += cur.x; p3 += cur.y; }
        p0 += __shfl_xor_sync(0xffffffffu, p0, 1);
        p1 += __shfl_xor_sync(0xffffffffu, p1, 1);
        p2 += __shfl_xor_sync(0xffffffffu, p2, 1);
        p3 += __shfl_xor_sync(0xffffffffu, p3, 1);
        // branch-free: both halves now hold identical full sums
        float ig = sig_apx(p0);
        float fg = sig_apx(p1);
        float gg = tanh_apx(p2);
        float og = sig_apx(p3);
        c = fg * c + ig * gg;
        float h = og * tanh_apx(c);
        if (store) {
            hsm[(t + 1) & 1][u] = h;
            hout[(size_t)t * HID] = h;
        }
        seg_bar<BARID, BARCNT>();
    };

    const int STR = GATES / 2;   // float2 stride per t
    float2 r0 = __ldcs(pp + 0 * STR);
    float2 r1 = __ldcs(pp + 1 * STR);
    float2 r2 = __ldcs(pp + 2 * STR);
    float2 r3 = __ldcs(pp + 3 * STR);
    #pragma unroll 1
    for (int t = 0; t < TT; t += 4) {
        step(t + 0, r0); if (t + 4 < TT) r0 = __ldcs(pp + (size_t)(t + 4) * STR);
        step(t + 1, r1); if (t + 5 < TT) r1 = __ldcs(pp + (size_t)(t + 5) * STR);
        step(t + 2, r2); if (t + 6 < TT) r2 = __ldcs(pp + (size_t)(t + 6) * STR);
        step(t + 3, r3); if (t + 7 < TT) r3 = __ldcs(pp + (size_t)(t + 7) * STR);
    }
}

__global__ void __launch_bounds__(384, 1)
k_scan(const float* __restrict__ whh_rh, const float* __restrict__ whh_ra,
       const float* __restrict__ whh_lh, const float* __restrict__ whh_la) {
    __shared__ __align__(16) float hsm[2][HID];
    int b = blockIdx.x, tid = threadIdx.x;
    int u = tid >> 1, half = tid & 1;
    if (tid < HID) hsm[0][tid] = 0.f;
    __syncthreads();
    // warp ranges per segment: rh w0-3, ra w4-5, lh w6-9, la w10-11
    if (u < 64)       scan_seg<64, 0,   0,   1, 128>(whh_rh, b, u,       half, u, hsm);
    else if (u < 96)  scan_seg<32, 64,  256, 2, 64 >(whh_ra, b, u - 64,  half, u, hsm);
    else if (u < 160) scan_seg<64, 96,  384, 3, 128>(whh_lh, b, u - 96,  half, u, hsm);
    else              scan_seg<32, 160, 640, 4, 64 >(whh_la, b, u - 160, half, u, hsm);
}

// ---------------------------------------------------------------------------
// K4: attention + FC.  1 CTA/sample, 1024 threads.
// out layout: [0 : 128*250) = logits, [128*250 : +128*512) = weights
// ---------------------------------------------------------------------------
__global__ void __launch_bounds__(1024)
k_att(const float* __restrict__ att_w, const float* __restrict__ fc_w,
      const float* __restrict__ fc_b, float* __restrict__ out) {
    __shared__ float sw[HID];
    __shared__ float sc[TT];
    __shared__ float red[32];
    __shared__ float ctxp[4][HID];
    __shared__ float ctx[HID];
    __shared__ float sval;
    int b = blockIdx.x, tid = threadIdx.x;
    int lane = tid & 31, wid = tid >> 5;
    const float* hsb = g_hs + (size_t)b * TT * HID;

    if (tid < HID) sw[tid] = att_w[tid];
    __syncthreads();

    // scores: one warp per t, 32 warps (coalesced h reads)
    for (int t = wid; t < TT; t += 32) {
        const float* hr = hsb + (size_t)t * HID;
        float s = 0.f;
        #pragma unroll
        for (int k = 0; k < 6; k++) s += sw[lane + 32 * k] * hr[lane + 32 * k];
        #pragma unroll
        for (int o = 16; o > 0; o >>= 1) s += __shfl_xor_sync(0xffffffffu, s, o);
        if (lane == 0) sc[t] = s;
    }
    __syncthreads();

    // softmax over T (threads 0..511)
    float v = (tid < TT) ? sc[tid] : -1e30f;
    float m = v;
    #pragma unroll
    for (int o = 16; o > 0; o >>= 1) m = fmaxf(m, __shfl_xor_sync(0xffffffffu, m, o));
    if (lane == 0) red[wid] = m;
    __syncthreads();
    if (tid == 0) {
        float mm = red[0];
        #pragma unroll
        for (int i = 1; i < 32; i++) mm = fmaxf(mm, red[i]);
        sval = mm;
    }
    __syncthreads();
    float e = (tid < TT) ? __expf(v - sval) : 0.f;
    float s = e;
    #pragma unroll
    for (int o = 16; o > 0; o >>= 1) s += __shfl_xor_sync(0xffffffffu, s, o);
    if (lane == 0) red[wid] = s;
    __syncthreads();
    if (tid == 0) {
        float ss = 0.f;
        #pragma unroll
        for (int i = 0; i < 32; i++) ss += red[i];
        sval = ss;
    }
    __syncthreads();
    if (tid < TT) {
        float wgt = e * (1.f / sval);
        sc[tid] = wgt;
        out[BB * NCLS + b * TT + tid] = wgt;
    }
    __syncthreads();

    // context: four t-quarters in parallel (threads 0..767)
    if (tid < 4 * HID) {
        int grp = tid / HID;
        int k = tid - grp * HID;
        int tb = grp * (TT / 4);
        float acc = 0.f;
        #pragma unroll 8
        for (int t = tb; t < tb + TT / 4; t++) acc += sc[t] * hsb[(size_t)t * HID + k];
        ctxp[grp][k] = acc;
    }
    __syncthreads();
    if (tid < HID) ctx[tid] = ctxp[0][tid] + ctxp[1][tid] + ctxp[2][tid] + ctxp[3][tid];
    __syncthreads();

    // FC: 4 threads per class (k-split 48 each, combined via two shfls)
    {
        int cls = tid >> 2, part = tid & 3;
        bool valid = (cls < NCLS);
        const float* wr = fc_w + (size_t)(valid ? cls : 0) * HID + part * 48;
        const float* cx = ctx + part * 48;
        float acc = 0.f;
        #pragma unroll 8
        for (int k = 0; k < 48; k++) acc += cx[k] * wr[k];
        acc += __shfl_xor_sync(0xffffffffu, acc, 1);
        acc += __shfl_xor_sync(0xffffffffu, acc, 2);
        if (valid && part == 0) out[b * NCLS + cls] = acc + fc_b[cls];
    }
}

// ---------------------------------------------------------------------------
extern "C" void kernel_launch(void* const* d_in, const int* in_sizes, int n_in,
                              void* d_out, int out_size) {
    const float* x      = (const float*)d_in[0];
    const float* wih_rh = (const float*)d_in[1];
    const float* whh_rh = (const float*)d_in[2];
    const float* bih_rh = (const float*)d_in[3];
    const float* bhh_rh = (const float*)d_in[4];
    const float* wih_ra = (const float*)d_in[5];
    const float* whh_ra = (const float*)d_in[6];
    const float* bih_ra = (const float*)d_in[7];
    const float* bhh_ra = (const float*)d_in[8];
    const float* wih_lh = (const float*)d_in[9];
    const float* whh_lh = (const float*)d_in[10];
    const float* bih_lh = (const float*)d_in[11];
    const float* bhh_lh = (const float*)d_in[12];
    const float* wih_la = (const float*)d_in[13];
    const float* whh_la = (const float*)d_in[14];
    const float* bih_la = (const float*)d_in[15];
    const float* bhh_la = (const float*)d_in[16];
    const float* att_w  = (const float*)d_in[17];
    const float* fc_w   = (const float*)d_in[18];
    const float* fc_b   = (const float*)d_in[19];
    float* out = (float*)d_out;

    k_feat<<<(BB * TT + 255) / 256, 256>>>(x);
    k_ingemm<<<BB * 4, 768>>>(wih_rh, bih_rh, bhh_rh,
                              wih_ra, bih_ra, bhh_ra,
                              wih_lh, bih_lh, bhh_lh,
                              wih_la, bih_la, bhh_la);
    k_scan<<<BB, 384>>>(whh_rh, whh_ra, whh_lh, whh_la);
    k_att<<<BB, 1024>>>(att_w, fc_w, fc_b, out);
}

// round 12
// speedup vs baseline: 1.3395x; 1.0503x over previous
#include <cuda_runtime.h>
#include <cuda_bf16.h>

#define BB    128
#define TT    512
#define FEAT  96
#define GATES 768
#define HID   192
#define NCLS  250

// scratch (device globals; allocations are forbidden)
__device__ __align__(16) float g_feat[BB * TT * FEAT];     // 25 MB
__device__ __align__(16) float g_pre [BB * TT * GATES];    // 201 MB (streamed, evict-first)
__device__ __align__(16) float g_hs  [BB * TT * HID];      // 50 MB  (kept L2-resident)

// ---------------- packed f32x2 helpers ----------------
__device__ __forceinline__ unsigned long long pack2(float x, float y) {
    unsigned long long u;
    asm("mov.b64 %0, {%1, %2};" : "=l"(u) : "f"(x), "f"(y));
    return u;
}
__device__ __forceinline__ unsigned long long ffma2(unsigned long long a,
                                                    unsigned long long b,
                                                    unsigned long long c) {
    unsigned long long d;
    asm("fma.rn.f32x2 %0, %1, %2, %3;" : "=l"(d) : "l"(a), "l"(b), "l"(c));
    return d;
}
__device__ __forceinline__ unsigned long long add2(unsigned long long a,
                                                   unsigned long long b) {
    unsigned long long d;
    asm("add.rn.f32x2 %0, %1, %2;" : "=l"(d) : "l"(a), "l"(b));
    return d;
}
__device__ __forceinline__ float pairsum(unsigned long long a) {
    float x, y;
    asm("mov.b64 {%0, %1}, %2;" : "=f"(x), "=f"(y) : "l"(a));
    return x + y;
}
__device__ __forceinline__ float tanh_apx(float x) {
    float y;
    asm("tanh.approx.f32 %0, %1;" : "=f"(y) : "f"(x));
    return y;
}
__device__ __forceinline__ float sig_apx(float x) {
    return fmaf(tanh_apx(0.5f * x), 0.5f, 0.5f);
}

// ---------------------------------------------------------------------------
// K1: feature prep. One thread per (b,t).
// layout per (b,t): [0:42] right hand, [42:48] right arm, [48:90] left hand,
//                   [90:96] left arm   (matches LSTM order rh,ra,lh,la)
// ---------------------------------------------------------------------------
__global__ void __launch_bounds__(256) k_feat(const float* __restrict__ x) {
    int idx = blockIdx.x * 256 + threadIdx.x;
    if (idx >= BB * TT) return;
    const float* row = x + (size_t)idx * 266;
    float* out = g_feat + (size_t)idx * FEAT;

    // right hand: points 112..132 (floats 224..265), ref point 10 (floats 20,21)
    {
        float rx = row[20], ry = row[21];
        float mnx = 1e30f, mxx = -1e30f, mny = 1e30f, mxy = -1e30f;
        #pragma unroll
        for (int p = 0; p < 21; p++) {
            float px = row[224 + 2 * p], py = row[225 + 2 * p];
            mnx = fminf(mnx, px); mxx = fmaxf(mxx, px);
            mny = fminf(mny, py); mxy = fmaxf(mxy, py);
        }
        float s = fmaxf(mxx - mnx, mxy - mny);
        s = (s == 0.f) ? 1.f : s;
        float inv = 1.f / s;
        #pragma unroll
        for (int p = 0; p < 21; p++) {
            out[2 * p]     = (row[224 + 2 * p] - rx) * inv;
            out[2 * p + 1] = (row[225 + 2 * p] - ry) * inv;
        }
    }
    // right arm: points 6,8,10 (floats 12,16,20), ref point 0
    {
        float cx = row[0], cy = row[1];
        float x0 = row[12], y0 = row[13];
        float x1 = row[16], y1 = row[17];
        float x2 = row[20], y2 = row[21];
        float w = fmaxf(fmaxf(x0, x1), x2) - fminf(fminf(x0, x1), x2);
        float h = fmaxf(fmaxf(y0, y1), y2) - fminf(fminf(y0, y1), y2);
        float s = fmaxf(w, h); s = (s == 0.f) ? 1.f : s;
        float inv = 1.f / s;
        out[42] = (x0 - cx) * inv; out[43] = (y0 - cy) * inv;
        out[44] = (x1 - cx) * inv; out[45] = (y1 - cy) * inv;
        out[46] = (x2 - cx) * inv; out[47] = (y2 - cy) * inv;
    }
    // left hand: points 91..111 (floats 182..223), ref point 9 (floats 18,19)
    {
        float rx = row[18], ry = row[19];
        float mnx = 1e30f, mxx = -1e30f, mny = 1e30f, mxy = -1e30f;
        #pragma unroll
        for (int p = 0; p < 21; p++) {
            float px = row[182 + 2 * p], py = row[183 + 2 * p];
            mnx = fminf(mnx, px); mxx = fmaxf(mxx, px);
            mny = fminf(mny, py); mxy = fmaxf(mxy, py);
        }
        float s = fmaxf(mxx - mnx, mxy - mny);
        s = (s == 0.f) ? 1.f : s;
        float inv = 1.f / s;
        #pragma unroll
        for (int p = 0; p < 21; p++) {
            out[48 + 2 * p] = (row[182 + 2 * p] - rx) * inv;
            out[49 + 2 * p] = (row[183 + 2 * p] - ry) * inv;
        }
    }
    // left arm: points 5,7,9 (floats 10,14,18), ref point 0
    {
        float cx = row[0], cy = row[1];
        float x0 = row[10], y0 = row[11];
        float x1 = row[14], y1 = row[15];
        float x2 = row[18], y2 = row[19];
        float w = fmaxf(fmaxf(x0, x1), x2) - fminf(fminf(x0, x1), x2);
        float h = fmaxf(fmaxf(y0, y1), y2) - fminf(fminf(y0, y1), y2);
        float s = fmaxf(w, h); s = (s == 0.f) ? 1.f : s;
        float inv = 1.f / s;
        out[90] = (x0 - cx) * inv; out[91] = (y0 - cy) * inv;
        out[92] = (x1 - cx) * inv; out[93] = (y1 - cy) * inv;
        out[94] = (x2 - cx) * inv; out[95] = (y2 - cy) * inv;
    }
}

// ---------------------------------------------------------------------------
// K2: input GEMM.  pre[row][g] = (bih+bhh) + wih_row . feat[row]
// The GEMM ignores sample boundaries: rows are the flat 65536 (b,t) index.
// 591 CTAs x 111 rows = exactly ~4 full waves on 148 SMs (vs 3.46 ragged
// waves with sample-aligned tiles).  768 threads = one output column each
// (warp stores 128B coalesced); 2-row unroll for ILP; .cs stores so the
// 201MB stream doesn't evict g_hs from L2.
// ---------------------------------------------------------------------------
#define ROWS_PER_CTA 111
#define N_GEMM_CTAS  ((BB * TT + ROWS_PER_CTA - 1) / ROWS_PER_CTA)   // 591

__global__ void __launch_bounds__(768)
k_ingemm(const float* __restrict__ wih_rh, const float* __restrict__ bih_rh, const float* __restrict__ bhh_rh,
         const float* __restrict__ wih_ra, const float* __restrict__ bih_ra, const float* __restrict__ bhh_ra,
         const float* __restrict__ wih_lh, const float* __restrict__ bih_lh, const float* __restrict__ bhh_lh,
         const float* __restrict__ wih_la, const float* __restrict__ bih_la, const float* __restrict__ bhh_la) {
    __shared__ __align__(16) float fs[ROWS_PER_CTA * FEAT];   // 42.6 KB
    int r0 = blockIdx.x * ROWS_PER_CTA;
    int nrows = BB * TT - r0;
    if (nrows > ROWS_PER_CTA) nrows = ROWS_PER_CTA;
    if (nrows <= 0) return;                    // uniform across CTA
    int g = threadIdx.x;

    // stage feature rows (contiguous, float4 coalesced; nrows*96 % 4 == 0)
    {
        const float4* src4 = (const float4*)(g_feat + (size_t)r0 * FEAT);
        float4* dst4 = (float4*)fs;
        int n4 = nrows * FEAT / 4;
        for (int i = g; i < n4; i += 768) dst4[i] = src4[i];
    }

    int r, F, k0, H;
    const float *wih, *bih, *bhh;
    if (g < 256)      { r = g;       F = 42; k0 = 0;  H = 64; wih = wih_rh; bih = bih_rh; bhh = bhh_rh; }
    else if (g < 384) { r = g - 256; F = 6;  k0 = 42; H = 32; wih = wih_ra; bih = bih_ra; bhh = bhh_ra; }
    else if (g < 640) { r = g - 384; F = 42; k0 = 48; H = 64; wih = wih_lh; bih = bih_lh; bhh = bhh_lh; }
    else              { r = g - 640; F = 6;  k0 = 90; H = 32; wih = wih_la; bih = bih_la; bhh = bhh_la; }
    int ul = r >> 2, gate = r & 3;
    int row = gate * H + ul;
    float bias = bih[row] + bhh[row];
    float* po = g_pre + (size_t)r0 * GATES + g;
    __syncthreads();

    if (F == 42) {
        unsigned long long w[21];
        const float* wr = wih + row * 42;
        #pragma unroll
        for (int i = 0; i < 21; i++) {
            float2 v = *(const float2*)(wr + 2 * i);
            w[i] = pack2(v.x, v.y);
        }
        int t = 0;
        #pragma unroll 1
        for (; t + 2 <= nrows; t += 2) {
            const float* fpA = fs + t * FEAT + k0;          // 16B aligned
            const float* fpB = fpA + FEAT;
            unsigned long long a0 = 0ull, a1 = 0ull, b0 = 0ull, b1 = 0ull;
            #pragma unroll
            for (int i = 0; i < 10; i++) {
                ulonglong2 qA = *(const ulonglong2*)(fpA + 4 * i);
                ulonglong2 qB = *(const ulonglong2*)(fpB + 4 * i);
                a0 = ffma2(w[2 * i],     qA.x, a0);
                a1 = ffma2(w[2 * i + 1], qA.y, a1);
                b0 = ffma2(w[2 * i],     qB.x, b0);
                b1 = ffma2(w[2 * i + 1], qB.y, b1);
            }
            unsigned long long tA = *(const unsigned long long*)(fpA + 40);
            unsigned long long tB = *(const unsigned long long*)(fpB + 40);
            a0 = ffma2(w[20], tA, a0);
            b0 = ffma2(w[20], tB, b0);
            __stcs(po + (size_t)t * GATES,       bias + pairsum(add2(a0, a1)));
            __stcs(po + (size_t)(t + 1) * GATES, bias + pairsum(add2(b0, b1)));
        }
        if (t < nrows) {
            const float* fp = fs + t * FEAT + k0;
            unsigned long long a0 = 0ull, a1 = 0ull;
            #pragma unroll
            for (int i = 0; i < 10; i++) {
                ulonglong2 q = *(const ulonglong2*)(fp + 4 * i);
                a0 = ffma2(w[2 * i],     q.x, a0);
                a1 = ffma2(w[2 * i + 1], q.y, a1);
            }
            unsigned long long tl = *(const unsigned long long*)(fp + 40);
            a0 = ffma2(w[20], tl, a0);
            __stcs(po + (size_t)t * GATES, bias + pairsum(add2(a0, a1)));
        }
    } else {
        unsigned long long w[3];
        const float* wr = wih + row * 6;
        #pragma unroll
        for (int i = 0; i < 3; i++) {
            float2 v = *(const float2*)(wr + 2 * i);
            w[i] = pack2(v.x, v.y);
        }
        int t = 0;
        #pragma unroll 1
        for (; t + 2 <= nrows; t += 2) {
            const unsigned long long* fA = (const unsigned long long*)(fs + t * FEAT + k0);
            const unsigned long long* fB = (const unsigned long long*)(fs + (t + 1) * FEAT + k0);
            unsigned long long a = 0ull, bacc = 0ull;
            #pragma unroll
            for (int i = 0; i < 3; i++) {
                a    = ffma2(w[i], fA[i], a);
                bacc = ffma2(w[i], fB[i], bacc);
            }
            __stcs(po + (size_t)t * GATES,       bias + pairsum(a));
            __stcs(po + (size_t)(t + 1) * GATES, bias + pairsum(bacc));
        }
        if (t < nrows) {
            const unsigned long long* fA = (const unsigned long long*)(fs + t * FEAT + k0);
            unsigned long long a = 0ull;
            #pragma unroll
            for (int i = 0; i < 3; i++) a = ffma2(w[i], fA[i], a);
            __stcs(po + (size_t)t * GATES, bias + pairsum(a));
        }
    }
}

// ---------------------------------------------------------------------------
// K3: recurrent scan.  1 CTA/sample, 384 threads = 2 per hidden unit.
// Per-segment named barriers; weights in registers; h double-buffered in
// smem; depth-4 register prefetch ring on pre (.cs loads).
// Activations BRANCH-FREE on all lanes (after bfly both halves hold identical
// full gate sums); only the stores are predicated.
// ---------------------------------------------------------------------------
template<int BARID, int BARCNT>
__device__ __forceinline__ void seg_bar() {
    asm volatile("bar.sync %0, %1;" :: "n"(BARID), "n"(BARCNT) : "memory");
}

template<int H, int HB, int PB, int BARID, int BARCNT>
__device__ __forceinline__ void scan_seg(const float* __restrict__ whh, int b,
                                         int ul, int half, int u,
                                         float (*hsm)[HID]) {
    constexpr int HW = H / 2;    // floats per half-dot
    constexpr int NH = HW / 2;   // u64 per gate
    constexpr int NQ = NH / 2;   // ulonglong2 per gate
    unsigned long long w[4 * NH];
    #pragma unroll
    for (int gI = 0; gI < 4; gI++) {
        const float* rw = whh + (gI * H + ul) * H + half * HW;
        #pragma unroll
        for (int i = 0; i < NH; i++) {
            float2 v = *(const float2*)(rw + 2 * i);
            w[gI * NH + i] = pack2(v.x, v.y);
        }
    }
    const float2* pp = (const float2*)(g_pre + (size_t)b * TT * GATES + PB + ul * 4 + half * 2);
    float* hout = g_hs + (size_t)b * TT * HID + u;
    float c = 0.f;
    bool store = (half == 0);

    auto step = [&](int t, float2 cur) {
        const ulonglong2* hv = (const ulonglong2*)&hsm[t & 1][HB + half * HW];
        unsigned long long a0 = 0ull, a1 = 0ull, a2 = 0ull, a3 = 0ull;
        #pragma unroll
        for (int i = 0; i < NQ; i++) {
            ulonglong2 q = hv[i];
            a0 = ffma2(w[0 * NH + 2 * i],     q.x, a0);
            a0 = ffma2(w[0 * NH + 2 * i + 1], q.y, a0);
            a1 = ffma2(w[1 * NH + 2 * i],     q.x, a1);
            a1 = ffma2(w[1 * NH + 2 * i + 1], q.y, a1);
            a2 = ffma2(w[2 * NH + 2 * i],     q.x, a2);
            a2 = ffma2(w[2 * NH + 2 * i + 1], q.y, a2);
            a3 = ffma2(w[3 * NH + 2 * i],     q.x, a3);
            a3 = ffma2(w[3 * NH + 2 * i + 1], q.y, a3);
        }
        float p0 = pairsum(a0), p1 = pairsum(a1), p2 = pairsum(a2), p3 = pairsum(a3);
        if (half == 0) { p0 += cur.x; p1 += cur.y; }
        else           { p2 += cur.x; p3 += cur.y; }
        p0 += __shfl_xor_sync(0xffffffffu, p0, 1);
        p1 += __shfl_xor_sync(0xffffffffu, p1, 1);
        p2 += __shfl_xor_sync(0xffffffffu, p2, 1);
        p3 += __shfl_xor_sync(0xffffffffu, p3, 1);
        // branch-free: both halves now hold identical full sums
        float ig = sig_apx(p0);
        float fg = sig_apx(p1);
        float gg = tanh_apx(p2);
        float og = sig_apx(p3);
        c = fg * c + ig * gg;
        float h = og * tanh_apx(c);
        if (store) {
            hsm[(t + 1) & 1][u] = h;
            hout[(size_t)t * HID] = h;
        }
        seg_bar<BARID, BARCNT>();
    };

    const int STR = GATES / 2;   // float2 stride per t
    float2 r0 = __ldcs(pp + 0 * STR);
    float2 r1 = __ldcs(pp + 1 * STR);
    float2 r2 = __ldcs(pp + 2 * STR);
    float2 r3 = __ldcs(pp + 3 * STR);
    #pragma unroll 1
    for (int t = 0; t < TT; t += 4) {
        step(t + 0, r0); if (t + 4 < TT) r0 = __ldcs(pp + (size_t)(t + 4) * STR);
        step(t + 1, r1); if (t + 5 < TT) r1 = __ldcs(pp + (size_t)(t + 5) * STR);
        step(t + 2, r2); if (t + 6 < TT) r2 = __ldcs(pp + (size_t)(t + 6) * STR);
        step(t + 3, r3); if (t + 7 < TT) r3 = __ldcs(pp + (size_t)(t + 7) * STR);
    }
}

__global__ void __launch_bounds__(384, 1)
k_scan(const float* __restrict__ whh_rh, const float* __restrict__ whh_ra,
       const float* __restrict__ whh_lh, const float* __restrict__ whh_la) {
    __shared__ __align__(16) float hsm[2][HID];
    int b = blockIdx.x, tid = threadIdx.x;
    int u = tid >> 1, half = tid & 1;
    if (tid < HID) hsm[0][tid] = 0.f;
    __syncthreads();
    // warp ranges per segment: rh w0-3, ra w4-5, lh w6-9, la w10-11
    if (u < 64)       scan_seg<64, 0,   0,   1, 128>(whh_rh, b, u,       half, u, hsm);
    else if (u < 96)  scan_seg<32, 64,  256, 2, 64 >(whh_ra, b, u - 64,  half, u, hsm);
    else if (u < 160) scan_seg<64, 96,  384, 3, 128>(whh_lh, b, u - 96,  half, u, hsm);
    else              scan_seg<32, 160, 640, 4, 64 >(whh_la, b, u - 160, half, u, hsm);
}

// ---------------------------------------------------------------------------
// K4: attention + FC.  1 CTA/sample, 1024 threads.
// out layout: [0 : 128*250) = logits, [128*250 : +128*512) = weights
// ---------------------------------------------------------------------------
__global__ void __launch_bounds__(1024)
k_att(const float* __restrict__ att_w, const float* __restrict__ fc_w,
      const float* __restrict__ fc_b, float* __restrict__ out) {
    __shared__ float sw[HID];
    __shared__ float sc[TT];
    __shared__ float red[32];
    __shared__ float ctxp[4][HID];
    __shared__ float ctx[HID];
    __shared__ float sval;
    int b = blockIdx.x, tid = threadIdx.x;
    int lane = tid & 31, wid = tid >> 5;
    const float* hsb = g_hs + (size_t)b * TT * HID;

    if (tid < HID) sw[tid] = att_w[tid];
    __syncthreads();

    // scores: one warp per t, 32 warps (coalesced h reads)
    for (int t = wid; t < TT; t += 32) {
        const float* hr = hsb + (size_t)t * HID;
        float s = 0.f;
        #pragma unroll
        for (int k = 0; k < 6; k++) s += sw[lane + 32 * k] * hr[lane + 32 * k];
        #pragma unroll
        for (int o = 16; o > 0; o >>= 1) s += __shfl_xor_sync(0xffffffffu, s, o);
        if (lane == 0) sc[t] = s;
    }
    __syncthreads();

    // softmax over T (threads 0..511)
    float v = (tid < TT) ? sc[tid] : -1e30f;
    float m = v;
    #pragma unroll
    for (int o = 16; o > 0; o >>= 1) m = fmaxf(m, __shfl_xor_sync(0xffffffffu, m, o));
    if (lane == 0) red[wid] = m;
    __syncthreads();
    if (tid == 0) {
        float mm = red[0];
        #pragma unroll
        for (int i = 1; i < 32; i++) mm = fmaxf(mm, red[i]);
        sval = mm;
    }
    __syncthreads();
    float e = (tid < TT) ? __expf(v - sval) : 0.f;
    float s = e;
    #pragma unroll
    for (int o = 16; o > 0; o >>= 1) s += __shfl_xor_sync(0xffffffffu, s, o);
    if (lane == 0) red[wid] = s;
    __syncthreads();
    if (tid == 0) {
        float ss = 0.f;
        #pragma unroll
        for (int i = 0; i < 32; i++) ss += red[i];
        sval = ss;
    }
    __syncthreads();
    if (tid < TT) {
        float wgt = e * (1.f / sval);
        sc[tid] = wgt;
        out[BB * NCLS + b * TT + tid] = wgt;
    }
    __syncthreads();

    // context: four t-quarters in parallel (threads 0..767)
    if (tid < 4 * HID) {
        int grp = tid / HID;
        int k = tid - grp * HID;
        int tb = grp * (TT / 4);
        float acc = 0.f;
        #pragma unroll 8
        for (int t = tb; t < tb + TT / 4; t++) acc += sc[t] * hsb[(size_t)t * HID + k];
        ctxp[grp][k] = acc;
    }
    __syncthreads();
    if (tid < HID) ctx[tid] = ctxp[0][tid] + ctxp[1][tid] + ctxp[2][tid] + ctxp[3][tid];
    __syncthreads();

    // FC: 4 threads per class (k-split 48 each, combined via two shfls)
    {
        int cls = tid >> 2, part = tid & 3;
        bool valid = (cls < NCLS);
        const float* wr = fc_w + (size_t)(valid ? cls : 0) * HID + part * 48;
        const float* cx = ctx + part * 48;
        float acc = 0.f;
        #pragma unroll 8
        for (int k = 0; k < 48; k++) acc += cx[k] * wr[k];
        acc += __shfl_xor_sync(0xffffffffu, acc, 1);
        acc += __shfl_xor_sync(0xffffffffu, acc, 2);
        if (valid && part == 0) out[b * NCLS + cls] = acc + fc_b[cls];
    }
}

// ---------------------------------------------------------------------------
extern "C" void kernel_launch(void* const* d_in, const int* in_sizes, int n_in,
                              void* d_out, int out_size) {
    const float* x      = (const float*)d_in[0];
    const float* wih_rh = (const float*)d_in[1];
    const float* whh_rh = (const float*)d_in[2];
    const float* bih_rh = (const float*)d_in[3];
    const float* bhh_rh = (const float*)d_in[4];
    const float* wih_ra = (const float*)d_in[5];
    const float* whh_ra = (const float*)d_in[6];
    const float* bih_ra = (const float*)d_in[7];
    const float* bhh_ra = (const float*)d_in[8];
    const float* wih_lh = (const float*)d_in[9];
    const float* whh_lh = (const float*)d_in[10];
    const float* bih_lh = (const float*)d_in[11];
    const float* bhh_lh = (const float*)d_in[12];
    const float* wih_la = (const float*)d_in[13];
    const float* whh_la = (const float*)d_in[14];
    const float* bih_la = (const float*)d_in[15];
    const float* bhh_la = (const float*)d_in[16];
    const float* att_w  = (const float*)d_in[17];
    const float* fc_w   = (const float*)d_in[18];
    const float* fc_b   = (const float*)d_in[19];
    float* out = (float*)d_out;

    k_feat<<<(BB * TT + 255) / 256, 256>>>(x);
    k_ingemm<<<N_GEMM_CTAS, 768>>>(wih_rh, bih_rh, bhh_rh,
                                   wih_ra, bih_ra, bhh_ra,
                                   wih_lh, bih_lh, bhh_lh,
                                   wih_la, bih_la, bhh_la);
    k_scan<<<BB, 384>>>(whh_rh, whh_ra, whh_lh, whh_la);
    k_att<<<BB, 1024>>>(att_w, fc_w, fc_b, out);
}

// round 16
// speedup vs baseline: 1.4057x; 1.0494x over previous
#include <cuda_runtime.h>
#include <cuda_bf16.h>

#define BB    128
#define TT    512
#define FEAT  96
#define GATES 768
#define HID   192
#define NCLS  250

// scratch (device globals; allocations are forbidden)
__device__ __align__(16) float g_feat[BB * TT * FEAT];     // 25 MB
__device__ __align__(16) float g_pre [BB * TT * GATES];    // 201 MB (streamed, evict-first)
__device__ __align__(16) float g_hs  [BB * TT * HID];      // 50 MB  (kept L2-resident)

// ---------------- packed f32x2 helpers ----------------
__device__ __forceinline__ unsigned long long pack2(float x, float y) {
    unsigned long long u;
    asm("mov.b64 %0, {%1, %2};" : "=l"(u) : "f"(x), "f"(y));
    return u;
}
__device__ __forceinline__ unsigned long long ffma2(unsigned long long a,
                                                    unsigned long long b,
                                                    unsigned long long c) {
    unsigned long long d;
    asm("fma.rn.f32x2 %0, %1, %2, %3;" : "=l"(d) : "l"(a), "l"(b), "l"(c));
    return d;
}
__device__ __forceinline__ float pairsum(unsigned long long a) {
    float x, y;
    asm("mov.b64 {%0, %1}, %2;" : "=f"(x), "=f"(y) : "l"(a));
    return x + y;
}
__device__ __forceinline__ float tanh_apx(float x) {
    float y;
    asm("tanh.approx.f32 %0, %1;" : "=f"(y) : "f"(x));
    return y;
}
__device__ __forceinline__ float sig_apx(float x) {
    return fmaf(tanh_apx(0.5f * x), 0.5f, 0.5f);
}

// ---------------------------------------------------------------------------
// K1: feature prep. One thread per (b,t).
// layout per (b,t): [0:42] right hand, [42:48] right arm, [48:90] left hand,
//                   [90:96] left arm   (matches LSTM order rh,ra,lh,la)
// ---------------------------------------------------------------------------
__global__ void __launch_bounds__(256) k_feat(const float* __restrict__ x) {
    int idx = blockIdx.x * 256 + threadIdx.x;
    if (idx >= BB * TT) return;
    const float* row = x + (size_t)idx * 266;
    float* out = g_feat + (size_t)idx * FEAT;

    // right hand: points 112..132 (floats 224..265), ref point 10 (floats 20,21)
    {
        float rx = row[20], ry = row[21];
        float mnx = 1e30f, mxx = -1e30f, mny = 1e30f, mxy = -1e30f;
        #pragma unroll
        for (int p = 0; p < 21; p++) {
            float px = row[224 + 2 * p], py = row[225 + 2 * p];
            mnx = fminf(mnx, px); mxx = fmaxf(mxx, px);
            mny = fminf(mny, py); mxy = fmaxf(mxy, py);
        }
        float s = fmaxf(mxx - mnx, mxy - mny);
        s = (s == 0.f) ? 1.f : s;
        float inv = 1.f / s;
        #pragma unroll
        for (int p = 0; p < 21; p++) {
            out[2 * p]     = (row[224 + 2 * p] - rx) * inv;
            out[2 * p + 1] = (row[225 + 2 * p] - ry) * inv;
        }
    }
    // right arm: points 6,8,10 (floats 12,16,20), ref point 0
    {
        float cx = row[0], cy = row[1];
        float x0 = row[12], y0 = row[13];
        float x1 = row[16], y1 = row[17];
        float x2 = row[20], y2 = row[21];
        float w = fmaxf(fmaxf(x0, x1), x2) - fminf(fminf(x0, x1), x2);
        float h = fmaxf(fmaxf(y0, y1), y2) - fminf(fminf(y0, y1), y2);
        float s = fmaxf(w, h); s = (s == 0.f) ? 1.f : s;
        float inv = 1.f / s;
        out[42] = (x0 - cx) * inv; out[43] = (y0 - cy) * inv;
        out[44] = (x1 - cx) * inv; out[45] = (y1 - cy) * inv;
        out[46] = (x2 - cx) * inv; out[47] = (y2 - cy) * inv;
    }
    // left hand: points 91..111 (floats 182..223), ref point 9 (floats 18,19)
    {
        float rx = row[18], ry = row[19];
        float mnx = 1e30f, mxx = -1e30f, mny = 1e30f, mxy = -1e30f;
        #pragma unroll
        for (int p = 0; p < 21; p++) {
            float px = row[182 + 2 * p], py = row[183 + 2 * p];
            mnx = fminf(mnx, px); mxx = fmaxf(mxx, px);
            mny = fminf(mny, py); mxy = fmaxf(mxy, py);
        }
        float s = fmaxf(mxx - mnx, mxy - mny);
        s = (s == 0.f) ? 1.f : s;
        float inv = 1.f / s;
        #pragma unroll
        for (int p = 0; p < 21; p++) {
            out[48 + 2 * p] = (row[182 + 2 * p] - rx) * inv;
            out[49 + 2 * p] = (row[183 + 2 * p] - ry) * inv;
        }
    }
    // left arm: points 5,7,9 (floats 10,14,18), ref point 0
    {
        float cx = row[0], cy = row[1];
        float x0 = row[10], y0 = row[11];
        float x1 = row[14], y1 = row[15];
        float x2 = row[18], y2 = row[19];
        float w = fmaxf(fmaxf(x0, x1), x2) - fminf(fminf(x0, x1), x2);
        float h = fmaxf(fmaxf(y0, y1), y2) - fminf(fminf(y0, y1), y2);
        float s = fmaxf(w, h); s = (s == 0.f) ? 1.f : s;
        float inv = 1.f / s;
        out[90] = (x0 - cx) * inv; out[91] = (y0 - cy) * inv;
        out[92] = (x1 - cx) * inv; out[93] = (y1 - cy) * inv;
        out[94] = (x2 - cx) * inv; out[95] = (y2 - cy) * inv;
    }
}

// ---------------------------------------------------------------------------
// K2: input GEMM.  pre[row][c] = (bih+bhh) + wih_c . feat[row]
// 384 threads = one (unit, gate-PAIR) each: 2 adjacent output columns share
// ONE set of feature loads (halves LDS issue vs per-gate threads) and store
// as a single STG.64.  The 2 interleaved 21-deep FFMA2 chains issue every
// 2 cyc = FMA-pipe rate, so each warp saturates its pipe.
// 591 CTAs x 111 flat rows = ~4 full waves.  .cs stores keep g_hs L2-resident.
// ---------------------------------------------------------------------------
#define ROWS_PER_CTA 111
#define N_GEMM_CTAS  ((BB * TT + ROWS_PER_CTA - 1) / ROWS_PER_CTA)   // 591

__global__ void __launch_bounds__(384)
k_ingemm(const float* __restrict__ wih_rh, const float* __restrict__ bih_rh, const float* __restrict__ bhh_rh,
         const float* __restrict__ wih_ra, const float* __restrict__ bih_ra, const float* __restrict__ bhh_ra,
         const float* __restrict__ wih_lh, const float* __restrict__ bih_lh, const float* __restrict__ bhh_lh,
         const float* __restrict__ wih_la, const float* __restrict__ bih_la, const float* __restrict__ bhh_la) {
    __shared__ __align__(16) float fs[ROWS_PER_CTA * FEAT];   // 42.6 KB
    int r0 = blockIdx.x * ROWS_PER_CTA;
    int nrows = BB * TT - r0;
    if (nrows > ROWS_PER_CTA) nrows = ROWS_PER_CTA;
    if (nrows <= 0) return;
    int g = threadIdx.x;

    // stage feature rows (contiguous, float4 coalesced)
    {
        const float4* src4 = (const float4*)(g_feat + (size_t)r0 * FEAT);
        float4* dst4 = (float4*)fs;
        int n4 = nrows * FEAT / 4;
        for (int i = g; i < n4; i += 384) dst4[i] = src4[i];
    }

    // thread -> (segment, unit, gate-pair).  warps stay segment-uniform:
    // g 0..127 rh, 128..191 ra, 192..319 lh, 320..383 la
    int u, pair, F, k0, H, segbase;
    const float *wih, *bih, *bhh;
    if (g < 128)      { int r = g;       u = r >> 1; pair = r & 1; F = 42; k0 = 0;  H = 64; segbase = 0;   wih = wih_rh; bih = bih_rh; bhh = bhh_rh; }
    else if (g < 192) { int r = g - 128; u = r >> 1; pair = r & 1; F = 6;  k0 = 42; H = 32; segbase = 256; wih = wih_ra; bih = bih_ra; bhh = bhh_ra; }
    else if (g < 320) { int r = g - 192; u = r >> 1; pair = r & 1; F = 42; k0 = 48; H = 64; segbase = 384; wih = wih_lh; bih = bih_lh; bhh = bhh_lh; }
    else              { int r = g - 320; u = r >> 1; pair = r & 1; F = 6;  k0 = 90; H = 32; segbase = 640; wih = wih_la; bih = bih_la; bhh = bhh_la; }
    int row0 = (2 * pair)     * H + u;
    int row1 = (2 * pair + 1) * H + u;
    float bias0 = bih[row0] + bhh[row0];
    float bias1 = bih[row1] + bhh[row1];
    float* po = g_pre + (size_t)r0 * GATES + segbase + u * 4 + 2 * pair;  // 8B aligned
    __syncthreads();

    if (F == 42) {
        unsigned long long w0[21], w1[21];
        {
            const float* wr0 = wih + row0 * 42;
            const float* wr1 = wih + row1 * 42;
            #pragma unroll
            for (int i = 0; i < 21; i++) {
                float2 v0 = *(const float2*)(wr0 + 2 * i);
                float2 v1 = *(const float2*)(wr1 + 2 * i);
                w0[i] = pack2(v0.x, v0.y);
                w1[i] = pack2(v1.x, v1.y);
            }
        }
        #pragma unroll 1
        for (int t = 0; t < nrows; t++) {
            const float* fp = fs + t * FEAT + k0;   // 16B aligned (k0 = 0 or 48)
            unsigned long long a0 = 0ull, a1 = 0ull;
            #pragma unroll
            for (int i = 0; i < 10; i++) {
                ulonglong2 q = *(const ulonglong2*)(fp + 4 * i);
                a0 = ffma2(w0[2 * i],     q.x, a0);
                a0 = ffma2(w0[2 * i + 1], q.y, a0);
                a1 = ffma2(w1[2 * i],     q.x, a1);
                a1 = ffma2(w1[2 * i + 1], q.y, a1);
            }
            unsigned long long tl = *(const unsigned long long*)(fp + 40);
            a0 = ffma2(w0[20], tl, a0);
            a1 = ffma2(w1[20], tl, a1);
            float2 outv = make_float2(bias0 + pairsum(a0), bias1 + pairsum(a1));
            __stcs((float2*)(po + (size_t)t * GATES), outv);
        }
    } else {
        unsigned long long w0[3], w1[3];
        {
            const float* wr0 = wih + row0 * 6;
            const float* wr1 = wih + row1 * 6;
            #pragma unroll
            for (int i = 0; i < 3; i++) {
                float2 v0 = *(const float2*)(wr0 + 2 * i);
                float2 v1 = *(const float2*)(wr1 + 2 * i);
                w0[i] = pack2(v0.x, v0.y);
                w1[i] = pack2(v1.x, v1.y);
            }
        }
        #pragma unroll 1
        for (int t = 0; t < nrows; t++) {
            const unsigned long long* f2 = (const unsigned long long*)(fs + t * FEAT + k0);
            unsigned long long a0 = 0ull, a1 = 0ull;
            #pragma unroll
            for (int i = 0; i < 3; i++) {
                unsigned long long q = f2[i];
                a0 = ffma2(w0[i], q, a0);
                a1 = ffma2(w1[i], q, a1);
            }
            float2 outv = make_float2(bias0 + pairsum(a0), bias1 + pairsum(a1));
            __stcs((float2*)(po + (size_t)t * GATES), outv);
        }
    }
}

// ---------------------------------------------------------------------------
// K3: recurrent scan.  1 CTA/sample, 384 threads = 2 per hidden unit.
// Per-segment named barriers; weights in registers; h double-buffered in
// smem; depth-4 register prefetch ring on pre (.cs loads).
// Activations BRANCH-FREE on all lanes (after bfly both halves hold identical
// full gate sums); only the stores are predicated.
// ---------------------------------------------------------------------------
template<int BARID, int BARCNT>
__device__ __forceinline__ void seg_bar() {
    asm volatile("bar.sync %0, %1;" :: "n"(BARID), "n"(BARCNT) : "memory");
}

template<int H, int HB, int PB, int BARID, int BARCNT>
__device__ __forceinline__ void scan_seg(const float* __restrict__ whh, int b,
                                         int ul, int half, int u,
                                         float (*hsm)[HID]) {
    constexpr int HW = H / 2;    // floats per half-dot
    constexpr int NH = HW / 2;   // u64 per gate
    constexpr int NQ = NH / 2;   // ulonglong2 per gate
    unsigned long long w[4 * NH];
    #pragma unroll
    for (int gI = 0; gI < 4; gI++) {
        const float* rw = whh + (gI * H + ul) * H + half * HW;
        #pragma unroll
        for (int i = 0; i < NH; i++) {
            float2 v = *(const float2*)(rw + 2 * i);
            w[gI * NH + i] = pack2(v.x, v.y);
        }
    }
    const float2* pp = (const float2*)(g_pre + (size_t)b * TT * GATES + PB + ul * 4 + half * 2);
    float* hout = g_hs + (size_t)b * TT * HID + u;
    float c = 0.f;
    bool store = (half == 0);

    auto step = [&](int t, float2 cur) {
        const ulonglong2* hv = (const ulonglong2*)&hsm[t & 1][HB + half * HW];
        unsigned long long a0 = 0ull, a1 = 0ull, a2 = 0ull, a3 = 0ull;
        #pragma unroll
        for (int i = 0; i < NQ; i++) {
            ulonglong2 q = hv[i];
            a0 = ffma2(w[0 * NH + 2 * i],     q.x, a0);
            a0 = ffma2(w[0 * NH + 2 * i + 1], q.y, a0);
            a1 = ffma2(w[1 * NH + 2 * i],     q.x, a1);
            a1 = ffma2(w[1 * NH + 2 * i + 1], q.y, a1);
            a2 = ffma2(w[2 * NH + 2 * i],     q.x, a2);
            a2 = ffma2(w[2 * NH + 2 * i + 1], q.y, a2);
            a3 = ffma2(w[3 * NH + 2 * i],     q.x, a3);
            a3 = ffma2(w[3 * NH + 2 * i + 1], q.y, a3);
        }
        float p0 = pairsum(a0), p1 = pairsum(a1), p2 = pairsum(a2), p3 = pairsum(a3);
        if (half == 0) { p0 += cur.x; p1 += cur.y; }
        else           { p2 += cur.x; p3 += cur.y; }
        p0 += __shfl_xor_sync(0xffffffffu, p0, 1);
        p1 += __shfl_xor_sync(0xffffffffu, p1, 1);
        p2 += __shfl_xor_sync(0xffffffffu, p2, 1);
        p3 += __shfl_xor_sync(0xffffffffu, p3, 1);
        // branch-free: both halves now hold identical full sums
        float ig = sig_apx(p0);
        float fg = sig_apx(p1);
        float gg = tanh_apx(p2);
        float og = sig_apx(p3);
        c = fg * c + ig * gg;
        float h = og * tanh_apx(c);
        if (store) {
            hsm[(t + 1) & 1][u] = h;
            hout[(size_t)t * HID] = h;
        }
        seg_bar<BARID, BARCNT>();
    };

    const int STR = GATES / 2;   // float2 stride per t
    float2 r0 = __ldcs(pp + 0 * STR);
    float2 r1 = __ldcs(pp + 1 * STR);
    float2 r2 = __ldcs(pp + 2 * STR);
    float2 r3 = __ldcs(pp + 3 * STR);
    #pragma unroll 1
    for (int t = 0; t < TT; t += 4) {
        step(t + 0, r0); if (t + 4 < TT) r0 = __ldcs(pp + (size_t)(t + 4) * STR);
        step(t + 1, r1); if (t + 5 < TT) r1 = __ldcs(pp + (size_t)(t + 5) * STR);
        step(t + 2, r2); if (t + 6 < TT) r2 = __ldcs(pp + (size_t)(t + 6) * STR);
        step(t + 3, r3); if (t + 7 < TT) r3 = __ldcs(pp + (size_t)(t + 7) * STR);
    }
}

__global__ void __launch_bounds__(384, 1)
k_scan(const float* __restrict__ whh_rh, const float* __restrict__ whh_ra,
       const float* __restrict__ whh_lh, const float* __restrict__ whh_la) {
    __shared__ __align__(16) float hsm[2][HID];
    int b = blockIdx.x, tid = threadIdx.x;
    int u = tid >> 1, half = tid & 1;
    if (tid < HID) hsm[0][tid] = 0.f;
    __syncthreads();
    // warp ranges per segment: rh w0-3, ra w4-5, lh w6-9, la w10-11
    if (u < 64)       scan_seg<64, 0,   0,   1, 128>(whh_rh, b, u,       half, u, hsm);
    else if (u < 96)  scan_seg<32, 64,  256, 2, 64 >(whh_ra, b, u - 64,  half, u, hsm);
    else if (u < 160) scan_seg<64, 96,  384, 3, 128>(whh_lh, b, u - 96,  half, u, hsm);
    else              scan_seg<32, 160, 640, 4, 64 >(whh_la, b, u - 160, half, u, hsm);
}

// ---------------------------------------------------------------------------
// K4: attention + FC.  1 CTA/sample, 1024 threads.
// out layout: [0 : 128*250) = logits, [128*250 : +128*512) = weights
// ---------------------------------------------------------------------------
__global__ void __launch_bounds__(1024)
k_att(const float* __restrict__ att_w, const float* __restrict__ fc_w,
      const float* __restrict__ fc_b, float* __restrict__ out) {
    __shared__ float sw[HID];
    __shared__ float sc[TT];
    __shared__ float red[32];
    __shared__ float ctxp[4][HID];
    __shared__ float ctx[HID];
    __shared__ float sval;
    int b = blockIdx.x, tid = threadIdx.x;
    int lane = tid & 31, wid = tid >> 5;
    const float* hsb = g_hs + (size_t)b * TT * HID;

    if (tid < HID) sw[tid] = att_w[tid];
    __syncthreads();

    // scores: one warp per t, 32 warps (coalesced h reads)
    for (int t = wid; t < TT; t += 32) {
        const float* hr = hsb + (size_t)t * HID;
        float s = 0.f;
        #pragma unroll
        for (int k = 0; k < 6; k++) s += sw[lane + 32 * k] * hr[lane + 32 * k];
        #pragma unroll
        for (int o = 16; o > 0; o >>= 1) s += __shfl_xor_sync(0xffffffffu, s, o);
        if (lane == 0) sc[t] = s;
    }
    __syncthreads();

    // softmax over T (threads 0..511)
    float v = (tid < TT) ? sc[tid] : -1e30f;
    float m = v;
    #pragma unroll
    for (int o = 16; o > 0; o >>= 1) m = fmaxf(m, __shfl_xor_sync(0xffffffffu, m, o));
    if (lane == 0) red[wid] = m;
    __syncthreads();
    if (tid == 0) {
        float mm = red[0];
        #pragma unroll
        for (int i = 1; i < 32; i++) mm = fmaxf(mm, red[i]);
        sval = mm;
    }
    __syncthreads();
    float e = (tid < TT) ? __expf(v - sval) : 0.f;
    float s = e;
    #pragma unroll
    for (int o = 16; o > 0; o >>= 1) s += __shfl_xor_sync(0xffffffffu, s, o);
    if (lane == 0) red[wid] = s;
    __syncthreads();
    if (tid == 0) {
        float ss = 0.f;
        #pragma unroll
        for (int i = 0; i < 32; i++) ss += red[i];
        sval = ss;
    }
    __syncthreads();
    if (tid < TT) {
        float wgt = e * (1.f / sval);
        sc[tid] = wgt;
        out[BB * NCLS + b * TT + tid] = wgt;
    }
    __syncthreads();

    // context: four t-quarters in parallel (threads 0..767)
    if (tid < 4 * HID) {
        int grp = tid / HID;
        int k = tid - grp * HID;
        int tb = grp * (TT / 4);
        float acc = 0.f;
        #pragma unroll 8
        for (int t = tb; t < tb + TT / 4; t++) acc += sc[t] * hsb[(size_t)t * HID + k];
        ctxp[grp][k] = acc;
    }
    __syncthreads();
    if (tid < HID) ctx[tid] = ctxp[0][tid] + ctxp[1][tid] + ctxp[2][tid] + ctxp[3][tid];
    __syncthreads();

    // FC: 4 threads per class (k-split 48 each, combined via two shfls)
    {
        int cls = tid >> 2, part = tid & 3;
        bool valid = (cls < NCLS);
        const float* wr = fc_w + (size_t)(valid ? cls : 0) * HID + part * 48;
        const float* cx = ctx + part * 48;
        float acc = 0.f;
        #pragma unroll 8
        for (int k = 0; k < 48; k++) acc += cx[k] * wr[k];
        acc += __shfl_xor_sync(0xffffffffu, acc, 1);
        acc += __shfl_xor_sync(0xffffffffu, acc, 2);
        if (valid && part == 0) out[b * NCLS + cls] = acc + fc_b[cls];
    }
}

// ---------------------------------------------------------------------------
extern "C" void kernel_launch(void* const* d_in, const int* in_sizes, int n_in,
                              void* d_out, int out_size) {
    const float* x      = (const float*)d_in[0];
    const float* wih_rh = (const float*)d_in[1];
    const float* whh_rh = (const float*)d_in[2];
    const float* bih_rh = (const float*)d_in[3];
    const float* bhh_rh = (const float*)d_in[4];
    const float* wih_ra = (const float*)d_in[5];
    const float* whh_ra = (const float*)d_in[6];
    const float* bih_ra = (const float*)d_in[7];
    const float* bhh_ra = (const float*)d_in[8];
    const float* wih_lh = (const float*)d_in[9];
    const float* whh_lh = (const float*)d_in[10];
    const float* bih_lh = (const float*)d_in[11];
    const float* bhh_lh = (const float*)d_in[12];
    const float* wih_la = (const float*)d_in[13];
    const float* whh_la = (const float*)d_in[14];
    const float* bih_la = (const float*)d_in[15];
    const float* bhh_la = (const float*)d_in[16];
    const float* att_w  = (const float*)d_in[17];
    const float* fc_w   = (const float*)d_in[18];
    const float* fc_b   = (const float*)d_in[19];
    float* out = (float*)d_out;

    k_feat<<<(BB * TT + 255) / 256, 256>>>(x);
    k_ingemm<<<N_GEMM_CTAS, 384>>>(wih_rh, bih_rh, bhh_rh,
                                   wih_ra, bih_ra, bhh_ra,
                                   wih_lh, bih_lh, bhh_lh,
                                   wih_la, bih_la, bhh_la);
    k_scan<<<BB, 384>>>(whh_rh, whh_ra, whh_lh, whh_la);
    k_att<<<BB, 1024>>>(att_w, fc_w, fc_b, out);
}